// round 11
// baseline (speedup 1.0000x reference)
#include <cuda_runtime.h>
#include <cuda_fp16.h>
#include <cstdint>
#include <math_constants.h>

#define NN 100000
#define EE 600000
#define DD 128
#define EPSLN 1e-5f
#define PADK 72    // smem row stride in halves for 64-col tiles (144B, conflict-free ldmatrix)
#define PLANE ((size_t)(NN + 128) * DD)   // padded hi/lo plane (tail rows read as 0)

// ---------------- scratch (device globals) -------------------------------------
__device__ float g_y[6L * NN * DD];          // 6 y planes (for z=6 batched GEMMs)
__device__ float g_statsA[9 * 2 * 3 * DD];   // 9 op slots x (sum, sumsq) x 3 x 128
__device__ int   g_deg[NN];
__device__ int   g_rowptr[NN + 1];
__device__ int   g_cursor[NN];
__device__ int   g_ssrc[EE];
__device__ int   g_bsums[256];
__device__ __half g_wpre[27L * 16384];       // per matrix: fp16 W^T [f*128+d]
// hi/lo candidate planes; slots: 0=pre0/aggB-mean 1=pre1/agg-mean 2=pre2/agg-max
//                                3=hin/aggB-max 4=s0 5=s1 6=m0 7=m1 8=sl
__device__ __half g_hlhi[9 * PLANE];
__device__ __half g_hllo[9 * PLANE];

// ---------------- helpers ------------------------------------------------------
__device__ __forceinline__ uint32_t smem_u32(const void* p) {
    uint32_t a;
    asm("{ .reg .u64 t; cvta.to.shared.u64 t, %1; cvt.u32.u64 %0, t; }" : "=r"(a) : "l"(p));
    return a;
}
__device__ __forceinline__ uint32_t pkh(__half a, __half b) {
    return (uint32_t)__half_as_ushort(a) | ((uint32_t)__half_as_ushort(b) << 16);
}
__device__ __forceinline__ void split4(float4 v, uint2& hi, uint2& lo) {
    __half h0 = __float2half_rn(v.x), h1 = __float2half_rn(v.y);
    __half h2 = __float2half_rn(v.z), h3 = __float2half_rn(v.w);
    __half l0 = __float2half_rn(v.x - __half2float(h0));
    __half l1 = __float2half_rn(v.y - __half2float(h1));
    __half l2 = __float2half_rn(v.z - __half2float(h2));
    __half l3 = __float2half_rn(v.w - __half2float(h3));
    hi = make_uint2(pkh(h0, h1), pkh(h2, h3));
    lo = make_uint2(pkh(l0, l1), pkh(l2, l3));
}
__device__ __forceinline__ float4 join4(uint2 hi, uint2 lo) {
    __half2 h01 = *(__half2*)&hi.x, h23 = *(__half2*)&hi.y;
    __half2 l01 = *(__half2*)&lo.x, l23 = *(__half2*)&lo.y;
    float2 a = __half22float2(h01), b = __half22float2(h23);
    float2 c = __half22float2(l01), d = __half22float2(l23);
    return make_float4(a.x + c.x, a.y + c.y, b.x + d.x, b.y + d.y);
}
__device__ __forceinline__ void ldsm_x4(uint32_t& r0, uint32_t& r1, uint32_t& r2, uint32_t& r3,
                                        uint32_t addr) {
    asm volatile("ldmatrix.sync.aligned.m8n8.x4.shared.b16 {%0, %1, %2, %3}, [%4];"
                 : "=r"(r0), "=r"(r1), "=r"(r2), "=r"(r3) : "r"(addr));
}
__device__ __forceinline__ void mma16816h(float* c, const uint32_t* a, const uint32_t* b) {
    asm volatile(
        "mma.sync.aligned.m16n8k16.row.col.f32.f16.f16.f32 "
        "{%0, %1, %2, %3}, {%4, %5, %6, %7}, {%8, %9}, {%0, %1, %2, %3};"
        : "+f"(c[0]), "+f"(c[1]), "+f"(c[2]), "+f"(c[3])
        : "r"(a[0]), "r"(a[1]), "r"(a[2]), "r"(a[3]), "r"(b[0]), "r"(b[1]));
}
__device__ __forceinline__ void cpasync16(uint32_t saddr, const void* gaddr) {
    asm volatile("cp.async.cg.shared.global [%0], [%1], 16;" :: "r"(saddr), "l"(gaddr));
}
__device__ __forceinline__ void cpasync_commit() {
    asm volatile("cp.async.commit_group;");
}
__device__ __forceinline__ void cpasync_wait0() {
    asm volatile("cp.async.wait_group 0;");
}

// ---------------- weight prep: W[d][f] fp32 -> fp16 W^T[f][d] -------------------
__global__ void k_wprep(const float* __restrict__ W, __half* __restrict__ out,
                        float* statszero, int zn) {
    if (statszero && blockIdx.x == 0) {
        for (int i = threadIdx.x; i < zn; i += blockDim.x) statszero[i] = 0.f;
    }
    int m = blockIdx.x >> 3;
    int part = blockIdx.x & 7;
    const float* src = W + (size_t)m * 16384;
    __half* oh = out + (size_t)m * 16384;
    int base = part * 2048;
    for (int i = threadIdx.x; i < 2048; i += blockDim.x) {
        int idx = base + i;
        int d = idx >> 7, f = idx & 127;
        oh[f * 128 + d] = __float2half_rn(src[idx]);
    }
}

// ---------------- zero-op candidates -> hi/lo planes ---------------------------
__global__ void k_pre_hl(const float* __restrict__ a, const float* __restrict__ b,
                         __half* h0, __half* l0, __half* h1, __half* l1,
                         __half* h2, __half* l2, int total4) {
    int i4 = blockIdx.x * blockDim.x + threadIdx.x;
    if (i4 >= total4) return;
    float4 x = ((const float4*)a)[i4];
    float4 y = ((const float4*)b)[i4];
    uint2 hi, lo;
    split4(x, hi, lo);
    ((uint2*)h0)[i4] = hi; ((uint2*)l0)[i4] = lo;
    float4 d = make_float4(x.x - y.x, x.y - y.y, x.z - y.z, x.w - y.w);
    split4(d, hi, lo);
    ((uint2*)h1)[i4] = hi; ((uint2*)l1)[i4] = lo;
    float4 p = make_float4(x.x * y.x, x.y * y.y, x.z * y.z, x.w * y.w);
    split4(p, hi, lo);
    ((uint2*)h2)[i4] = hi; ((uint2*)l2)[i4] = lo;
}

// ---------------- fp16 2-pass tensor GEMM, double-buffered fills ----------------
// Up to 2 ops per launch (z = 3*nops). A fill = pure cp.async from hi/lo planes,
// next chunk's fill overlapped with current chunk's mma.
#define TILE_HALVES (128 * PADK)             // 9216 halves = 18432 B
#define BUFSET (3 * TILE_HALVES)             // Ahi+Alo+B per buffer set (halves)
#define SMEM_MMA (2 * BUFSET * 2 + 1024)     // 2 buffer sets + stats

__global__ __launch_bounds__(256, 2) void k_gemm_mma(
    const __half* __restrict__ a0h, const __half* __restrict__ a0l,
    const __half* __restrict__ a1h, const __half* __restrict__ a1l,
    const __half* __restrict__ a2h, const __half* __restrict__ a2l,
    const __half* __restrict__ b0h, const __half* __restrict__ b0l,
    const __half* __restrict__ b1h, const __half* __restrict__ b1l,
    const __half* __restrict__ b2h, const __half* __restrict__ b2l,
    const __half* __restrict__ wpre, const float* __restrict__ bias,
    float* __restrict__ Y, float* __restrict__ stats, int n, size_t ystride, int catmode)
{
    extern __shared__ char sm[];
    __half* base0 = (__half*)sm;
    float* ssum = (float*)(base0 + 2 * BUFSET);
    float* ssq  = ssum + 128;

    int tid = threadIdx.x;
    int wid = tid >> 5, lane = tid & 31;
    int wm_ = wid >> 1, wn_ = wid & 1;
    int z = blockIdx.z;
    int opsel = z / 3;
    int kcand = catmode ? 0 : (z % 3);
    int nchunk = catmode ? 3 : 1;
    int row0 = blockIdx.x * 128;
    float* Yk = Y + (size_t)(opsel * 3 + kcand) * ystride;
    const float* bk = bias + (opsel * 3 + kcand) * DD;
    float* st = stats + opsel * 768;
    int so = kcand * DD;

    if (tid < 128) { ssum[tid] = 0.f; ssq[tid] = 0.f; }

    float c[2][8][4];
    #pragma unroll
    for (int i = 0; i < 2; i++)
        #pragma unroll
        for (int j = 0; j < 8; j++)
            #pragma unroll
            for (int q = 0; q < 4; q++) c[i][j][q] = 0.f;

    int a_row = wm_ * 32 + (lane & 15);
    int a_k8 = (lane >> 4) * 8;
    int b_f = wn_ * 64 + ((lane >> 4) << 3) + (lane & 7);
    int b_k8 = ((lane >> 3) & 1) * 8;
    uint32_t ubase = smem_u32(base0);

    // candidate plane tables
    const __half* XHt[3];
    const __half* XLt[3];
    if (opsel == 0 || catmode) {
        XHt[0] = a0h; XHt[1] = a1h; XHt[2] = a2h;
        XLt[0] = a0l; XLt[1] = a1l; XLt[2] = a2l;
    } else {
        XHt[0] = b0h; XHt[1] = b1h; XHt[2] = b2h;
        XLt[0] = b0l; XLt[1] = b1l; XLt[2] = b2l;
    }

    int totchunks = nchunk * 2;
    int frow = tid >> 1, fsg = tid & 1;   // fill mapping: 2 threads/row, 64B per plane

    auto do_fill = [&](int tc, int buf) {
        int c3 = tc >> 1, ch = tc & 1;
        const __half* XH = catmode ? XHt[c3] : XHt[kcand];
        const __half* XL = catmode ? XLt[c3] : XLt[kcand];
        const __half* wmr = wpre + (size_t)(opsel * 3 + (catmode ? c3 : kcand)) * 16384;
        uint32_t bb = ubase + (uint32_t)(buf * BUFSET * 2);
        size_t gofs = ((size_t)(row0 + frow) * DD + ch * 64) * 2 + fsg * 64;
        uint32_t sofs = (uint32_t)(frow * PADK * 2 + fsg * 64);
        const char* sh = (const char*)XH + gofs;
        const char* sl = (const char*)XL + gofs;
        const char* sb = (const char*)wmr + ((size_t)frow * 128 + ch * 64) * 2 + fsg * 64;
        uint32_t dh = bb + sofs;
        uint32_t dl = bb + (uint32_t)(TILE_HALVES * 2) + sofs;
        uint32_t db = bb + (uint32_t)(2 * TILE_HALVES * 2) + sofs;
        #pragma unroll
        for (int q = 0; q < 4; q++) {
            cpasync16(dh + q * 16, sh + q * 16);
            cpasync16(dl + q * 16, sl + q * 16);
            cpasync16(db + q * 16, sb + q * 16);
        }
        cpasync_commit();
    };

    do_fill(0, 0);
    for (int tc = 0; tc < totchunks; tc++) {
        cpasync_wait0();
        __syncthreads();            // all warps done with previous mma + fill visible
        if (tc + 1 < totchunks) do_fill(tc + 1, (tc + 1) & 1);
        uint32_t bb = ubase + (uint32_t)((tc & 1) * BUFSET * 2);
        uint32_t uAhi = bb;
        uint32_t uAlo = bb + (uint32_t)(TILE_HALVES * 2);
        uint32_t uBh  = bb + (uint32_t)(2 * TILE_HALVES * 2);
        #pragma unroll
        for (int k = 0; k < 4; k++) {
            uint32_t ah[2][4], al[2][4];
            #pragma unroll
            for (int mt = 0; mt < 2; mt++) {
                uint32_t off = (uint32_t)(((a_row + mt * 16) * PADK + k * 16 + a_k8) * 2);
                ldsm_x4(ah[mt][0], ah[mt][1], ah[mt][2], ah[mt][3], uAhi + off);
                ldsm_x4(al[mt][0], al[mt][1], al[mt][2], al[mt][3], uAlo + off);
            }
            uint32_t b[4][4];
            #pragma unroll
            for (int p = 0; p < 4; p++) {
                uint32_t addr = uBh + (uint32_t)(((b_f + p * 16) * PADK + k * 16 + b_k8) * 2);
                ldsm_x4(b[p][0], b[p][1], b[p][2], b[p][3], addr);
            }
            #pragma unroll
            for (int mt = 0; mt < 2; mt++)
                #pragma unroll
                for (int nt = 0; nt < 8; nt++) {
                    mma16816h(c[mt][nt], ah[mt], &b[nt >> 1][(nt & 1) * 2]);
                    mma16816h(c[mt][nt], al[mt], &b[nt >> 1][(nt & 1) * 2]);
                }
        }
    }

    // ---------------- epilogue: bias, store Y, fused column stats ---------------
    int erow = lane >> 2, ecp = lane & 3;
    float2 bb2[8];
    #pragma unroll
    for (int nt = 0; nt < 8; nt++)
        bb2[nt] = *(const float2*)(bk + wn_ * 64 + nt * 8 + ecp * 2);

    float lsum[16], lsq[16];
    #pragma unroll
    for (int j = 0; j < 16; j++) { lsum[j] = 0.f; lsq[j] = 0.f; }

    #pragma unroll
    for (int mt = 0; mt < 2; mt++) {
        int r0g = row0 + wm_ * 32 + mt * 16 + erow;
        int r1g = r0g + 8;
        #pragma unroll
        for (int nt = 0; nt < 8; nt++) {
            int cbase = wn_ * 64 + nt * 8 + ecp * 2;
            float v00 = c[mt][nt][0] + bb2[nt].x;
            float v01 = c[mt][nt][1] + bb2[nt].y;
            float v10 = c[mt][nt][2] + bb2[nt].x;
            float v11 = c[mt][nt][3] + bb2[nt].y;
            if (r0g < n) {
                *(float2*)(Yk + (size_t)r0g * DD + cbase) = make_float2(v00, v01);
                lsum[nt * 2]     += v00; lsq[nt * 2]     += v00 * v00;
                lsum[nt * 2 + 1] += v01; lsq[nt * 2 + 1] += v01 * v01;
            }
            if (r1g < n) {
                *(float2*)(Yk + (size_t)r1g * DD + cbase) = make_float2(v10, v11);
                lsum[nt * 2]     += v10; lsq[nt * 2]     += v10 * v10;
                lsum[nt * 2 + 1] += v11; lsq[nt * 2 + 1] += v11 * v11;
            }
        }
    }
    #pragma unroll
    for (int nt = 0; nt < 8; nt++) {
        int cbase = wn_ * 64 + nt * 8 + ecp * 2;
        atomicAdd(&ssum[cbase],     lsum[nt * 2]);
        atomicAdd(&ssq[cbase],      lsq[nt * 2]);
        atomicAdd(&ssum[cbase + 1], lsum[nt * 2 + 1]);
        atomicAdd(&ssq[cbase + 1],  lsq[nt * 2 + 1]);
    }
    __syncthreads();
    if (tid < 128) {
        atomicAdd(&st[so + tid], ssum[tid]);
        atomicAdd(&st[3 * DD + so + tid], ssq[tid]);
    }
}

// ---------------- CSR build ---------------------------------------------------
__global__ void k_hist(const int* __restrict__ dst, int* deg, int e) {
    int i = blockIdx.x * blockDim.x + threadIdx.x;
    if (i < e) atomicAdd(&deg[dst[i]], 1);
}
__global__ void k_scan_block(const int* __restrict__ deg, int* incl, int* bsums, int n) {
    __shared__ int sh[1024];
    int i = blockIdx.x * 1024 + threadIdx.x;
    int v = (i < n) ? deg[i] : 0;
    sh[threadIdx.x] = v;
    __syncthreads();
    for (int off = 1; off < 1024; off <<= 1) {
        int t = (threadIdx.x >= off) ? sh[threadIdx.x - off] : 0;
        __syncthreads();
        sh[threadIdx.x] += t;
        __syncthreads();
    }
    if (i < n) incl[i] = sh[threadIdx.x];
    if (threadIdx.x == 1023) bsums[blockIdx.x] = sh[1023];
}
__global__ void k_scan_sums(int* bsums, int nb) {
    if (threadIdx.x == 0 && blockIdx.x == 0) {
        int run = 0;
        for (int i = 0; i < nb; i++) { int t = bsums[i]; bsums[i] = run; run += t; }
    }
}
__global__ void k_scan_fin(const int* __restrict__ deg, const int* __restrict__ incl,
                           const int* __restrict__ bsums, int* rowptr, int* cursor, int n, int e) {
    int i = blockIdx.x * blockDim.x + threadIdx.x;
    if (i < n) {
        int ex = incl[i] - deg[i] + bsums[i >> 10];
        rowptr[i] = ex;
        cursor[i] = ex;
        if (i == n - 1) rowptr[n] = e;
    }
}
__global__ void k_scatter(const int* __restrict__ src, const int* __restrict__ dst,
                          int* cursor, int* ssrc, int e) {
    int i = blockIdx.x * blockDim.x + threadIdx.x;
    if (i < e) {
        int p = atomicAdd(&cursor[dst[i]], 1);
        ssrc[p] = src[i];
    }
}

// ---------------- graph aggregation: planes in -> planes out, warp per node ----
__global__ void k_agg(const __half* __restrict__ hH, const __half* __restrict__ hL,
                      const int* __restrict__ rowptr, const int* __restrict__ ssrc,
                      __half* mhi, __half* mlo, __half* xhi, __half* xlo, int n) {
    int warp = (blockIdx.x * blockDim.x + threadIdx.x) >> 5;
    int lane = threadIdx.x & 31;
    if (warp >= n) return;
    int beg = rowptr[warp], end = rowptr[warp + 1];
    float4 s  = make_float4(0.f, 0.f, 0.f, 0.f);
    float4 mx = make_float4(-CUDART_INF_F, -CUDART_INF_F, -CUDART_INF_F, -CUDART_INF_F);
    for (int i = beg; i < end; i++) {
        int src = ssrc[i];
        uint2 hi = ((const uint2*)(hH + (size_t)src * DD))[lane];
        uint2 lo = ((const uint2*)(hL + (size_t)src * DD))[lane];
        float4 v = join4(hi, lo);
        s.x += v.x; s.y += v.y; s.z += v.z; s.w += v.w;
        mx.x = fmaxf(mx.x, v.x); mx.y = fmaxf(mx.y, v.y);
        mx.z = fmaxf(mx.z, v.z); mx.w = fmaxf(mx.w, v.w);
    }
    int deg = end - beg;
    float inv = 1.0f / (float)max(deg, 1);
    float4 mo = make_float4(s.x * inv, s.y * inv, s.z * inv, s.w * inv);
    float4 xo = (deg > 0) ? mx : make_float4(0.f, 0.f, 0.f, 0.f);
    uint2 hi, lo;
    split4(mo, hi, lo);
    ((uint2*)(mhi + (size_t)warp * DD))[lane] = hi;
    ((uint2*)(mlo + (size_t)warp * DD))[lane] = lo;
    split4(xo, hi, lo);
    ((uint2*)(xhi + (size_t)warp * DD))[lane] = hi;
    ((uint2*)(xlo + (size_t)warp * DD))[lane] = lo;
}

// ---------------- combine: normalize+relu+ksum -> hi/lo planes ------------------
__device__ __forceinline__ float4 mix3(const float* y, const float* stats,
                                       const float* wrow, const float* gg,
                                       const float* be, int i4, int d0, float fn,
                                       size_t plane_elts) {
    float4 acc = make_float4(0.f, 0.f, 0.f, 0.f);
    #pragma unroll
    for (int k = 0; k < 3; k++) {
        float wk = wrow[k];
        float4 v = ((const float4*)(y + (size_t)k * plane_elts))[i4];
        #pragma unroll
        for (int j = 0; j < 4; j++) {
            int d = d0 + j;
            float mu  = stats[k * DD + d] / fn;
            float var = stats[3 * DD + k * DD + d] / fn - mu * mu;
            float rs  = rsqrtf(var + EPSLN);
            float vv = (&v.x)[j];
            float t = (vv - mu) * rs * gg[k * DD + d] + be[k * DD + d];
            (&acc.x)[j] += wk * fmaxf(t, 0.f);
        }
    }
    return acc;
}

__global__ void k_combine1(const float* __restrict__ y, const float* __restrict__ stats,
                           const float* __restrict__ wrow, const float* __restrict__ gg,
                           const float* __restrict__ be,
                           __half* hiP, __half* loP, int n) {
    int i4 = blockIdx.x * blockDim.x + threadIdx.x;
    int total4 = (n * DD) >> 2;
    if (i4 >= total4) return;
    int d0 = (i4 << 2) & (DD - 1);
    float4 acc = mix3(y, stats, wrow, gg, be, i4, d0, (float)n, (size_t)n * DD);
    uint2 hi, lo;
    split4(acc, hi, lo);
    ((uint2*)hiP)[i4] = hi;
    ((uint2*)loP)[i4] = lo;
}

__global__ void k_combine2(const float* __restrict__ yA, const float* __restrict__ stA,
                           const float* __restrict__ wA, const float* __restrict__ gA,
                           const float* __restrict__ beA,
                           const float* __restrict__ yB, const float* __restrict__ stB,
                           const float* __restrict__ wB, const float* __restrict__ gB,
                           const float* __restrict__ beB,
                           __half* hiP, __half* loP, int n) {
    int i4 = blockIdx.x * blockDim.x + threadIdx.x;
    int total4 = (n * DD) >> 2;
    if (i4 >= total4) return;
    int d0 = (i4 << 2) & (DD - 1);
    float fn = (float)n;
    size_t pe = (size_t)n * DD;
    float4 a = mix3(yA, stA, wA, gA, beA, i4, d0, fn, pe);
    float4 b = mix3(yB, stB, wB, gB, beB, i4, d0, fn, pe);
    float4 acc = make_float4(a.x + b.x, a.y + b.y, a.z + b.z, a.w + b.w);
    uint2 hi, lo;
    split4(acc, hi, lo);
    ((uint2*)hiP)[i4] = hi;
    ((uint2*)loP)[i4] = lo;
}

// ---------------- final column-norm + relu ------------------------------------
__global__ void k_finalnorm(const float* __restrict__ h, const float* __restrict__ stats,
                            const float* __restrict__ gc, const float* __restrict__ bec,
                            float* __restrict__ out, int n) {
    int idx = blockIdx.x * blockDim.x + threadIdx.x;
    int total = n * DD;
    if (idx >= total) return;
    int d = idx & (DD - 1);
    float fn = (float)n;
    float mu  = stats[d] / fn;
    float var = stats[3 * DD + d] / fn - mu * mu;
    float rs  = rsqrtf(var + EPSLN);
    float v = (h[idx] - mu) * rs * gc[d] + bec[d];
    out[idx] = fmaxf(v, 0.f);
}

// ---------------- host orchestration ------------------------------------------
extern "C" void kernel_launch(void* const* d_in, const int* in_sizes, int n_in,
                              void* d_out, int out_size) {
    const float* src_emb = (const float*)d_in[0];
    const float* hr      = (const float*)d_in[1];
    const int*   esrc    = (const int*)d_in[2];
    const int*   edst    = (const int*)d_in[3];
    const float* w_zero  = (const float*)d_in[4];
    const float* w_first = (const float*)d_in[5];
    const float* w_mid   = (const float*)d_in[6];
    const float* w_last  = (const float*)d_in[7];
    const float* W_zero  = (const float*)d_in[8];
    const float* b_zero  = (const float*)d_in[9];
    const float* g_zeroP = (const float*)d_in[10];
    const float* be_zero = (const float*)d_in[11];
    const float* W_first = (const float*)d_in[12];
    const float* b_first = (const float*)d_in[13];
    const float* g_firstP= (const float*)d_in[14];
    const float* be_first= (const float*)d_in[15];
    const float* W_mid   = (const float*)d_in[16];
    const float* b_mid   = (const float*)d_in[17];
    const float* g_midP  = (const float*)d_in[18];
    const float* be_mid  = (const float*)d_in[19];
    const float* W_last  = (const float*)d_in[20];
    const float* b_last  = (const float*)d_in[21];
    const float* g_lastP = (const float*)d_in[22];
    const float* be_last = (const float*)d_in[23];
    const float* W_cat   = (const float*)d_in[24];
    const float* b_cat   = (const float*)d_in[25];
    const float* g_cat   = (const float*)d_in[26];
    const float* be_cat  = (const float*)d_in[27];

    int n = in_sizes[0] / DD;
    int e = in_sizes[2];

    float *yb, *statsA;
    int *deg, *rowptr, *cursor, *ssrc, *bsums;
    __half *wpre, *hlhi, *hllo;
    cudaGetSymbolAddress((void**)&yb, g_y);
    cudaGetSymbolAddress((void**)&statsA, g_statsA);
    cudaGetSymbolAddress((void**)&deg, g_deg);
    cudaGetSymbolAddress((void**)&rowptr, g_rowptr);
    cudaGetSymbolAddress((void**)&cursor, g_cursor);
    cudaGetSymbolAddress((void**)&ssrc, g_ssrc);
    cudaGetSymbolAddress((void**)&bsums, g_bsums);
    cudaGetSymbolAddress((void**)&wpre, g_wpre);
    cudaGetSymbolAddress((void**)&hlhi, g_hlhi);
    cudaGetSymbolAddress((void**)&hllo, g_hllo);

    cudaFuncSetAttribute(k_gemm_mma, cudaFuncAttributeMaxDynamicSharedMemorySize, SMEM_MMA);

    auto HI = [&](int s) { return hlhi + (size_t)s * PLANE; };
    auto LO = [&](int s) { return hllo + (size_t)s * PLANE; };
    auto ST = [&](int s) { return statsA + (size_t)s * 768; };

    int total = n * DD;
    size_t ystride = (size_t)n * DD;
    int gtiles = (n + 127) / 128;
    int ew_grid = (total + 255) / 256;
    int ew_grid4 = (total / 4 + 255) / 256;
    int agg_grid = (n + 7) / 8;
    int eb = (e + 255) / 256;
    int nb1024 = (n + 1023) / 1024;

    // ---- weight prep (stats slots zeroed in first launch) ----
    k_wprep<<<3 * 8, 256>>>(W_zero,  wpre + 0L  * 16384, statsA, 9 * 768);
    k_wprep<<<9 * 8, 256>>>(W_first, wpre + 3L  * 16384, nullptr, 0);
    k_wprep<<<6 * 8, 256>>>(W_mid,   wpre + 12L * 16384, nullptr, 0);
    k_wprep<<<6 * 8, 256>>>(W_last,  wpre + 18L * 16384, nullptr, 0);
    k_wprep<<<3 * 8, 256>>>(W_cat,   wpre + 24L * 16384, nullptr, 0);

    auto gemm1 = [&](int c0, int c1, int c2, int opmat, const float* B, int stslot) {
        k_gemm_mma<<<dim3(gtiles, 1, 3), 256, SMEM_MMA>>>(
            HI(c0), LO(c0), HI(c1), LO(c1), HI(c2), LO(c2),
            nullptr, nullptr, nullptr, nullptr, nullptr, nullptr,
            wpre + (size_t)opmat * 16384, B, yb, ST(stslot), n, ystride, 0);
    };
    auto gemm2 = [&](int a0, int a1, int a2, int b0, int b1, int b2,
                     int opmat, const float* B, int stslot) {
        k_gemm_mma<<<dim3(gtiles, 1, 6), 256, SMEM_MMA>>>(
            HI(a0), LO(a0), HI(a1), LO(a1), HI(a2), LO(a2),
            HI(b0), LO(b0), HI(b1), LO(b1), HI(b2), LO(b2),
            wpre + (size_t)opmat * 16384, B, yb, ST(stslot), n, ystride, 0);
    };

    // ---- zero op: pre candidates into slots 0,1,2; hin -> slot 3 ----
    k_pre_hl<<<ew_grid4, 256>>>(src_emb, hr, HI(0), LO(0), HI(1), LO(1), HI(2), LO(2), total / 4);
    gemm1(0, 1, 2, 0, b_zero, 0);

    // ---- CSR build ----
    cudaMemsetAsync(deg, 0, (size_t)n * sizeof(int));
    k_hist<<<eb, 256>>>(edst, deg, e);
    k_scan_block<<<nb1024, 1024>>>(deg, cursor, bsums, n);
    k_scan_sums<<<1, 32>>>(bsums, nb1024);
    k_scan_fin<<<(n + 255) / 256, 256>>>(deg, cursor, bsums, rowptr, cursor, n, e);
    k_scatter<<<eb, 256>>>(esrc, edst, cursor, ssrc, e);

    k_combine1<<<ew_grid4, 256>>>(yb, ST(0), w_zero, g_zeroP, be_zero, HI(3), LO(3), n);

    // ---- first ops ----
    k_agg<<<agg_grid, 256>>>(HI(3), LO(3), rowptr, ssrc, HI(1), LO(1), HI(2), LO(2), n);
    gemm2(3, 1, 2, 3, 1, 2, 3, b_first, 1);
    k_combine1<<<ew_grid4, 256>>>(yb, ST(1), w_first + 0, g_firstP + 0 * 3 * DD,
                                  be_first + 0 * 3 * DD, HI(4), LO(4), n);   // s0
    k_agg<<<agg_grid, 256>>>(HI(4), LO(4), rowptr, ssrc, HI(1), LO(1), HI(2), LO(2), n);
    gemm1(4, 1, 2, 9, b_first + 6 * DD, 3);
    k_combine2<<<ew_grid4, 256>>>(
        yb + 3 * ystride, ST(2), w_first + 3, g_firstP + 1 * 3 * DD, be_first + 1 * 3 * DD,
        yb, ST(3), w_first + 6, g_firstP + 2 * 3 * DD, be_first + 2 * 3 * DD,
        HI(5), LO(5), n);                                    // s1

    // ---- middle ops ---- (agg(s0) still in slots 1,2)
    gemm1(4, 1, 2, 12, b_mid, 4);
    k_combine1<<<ew_grid4, 256>>>(yb, ST(4), w_mid + 0, g_midP + 0 * 3 * DD,
                                  be_mid + 0 * 3 * DD, HI(6), LO(6), n);     // m0
    k_agg<<<agg_grid, 256>>>(HI(5), LO(5), rowptr, ssrc, HI(1), LO(1), HI(2), LO(2), n);
    gemm1(5, 1, 2, 15, b_mid + 3 * DD, 5);
    k_combine1<<<ew_grid4, 256>>>(yb, ST(5), w_mid + 3, g_midP + 1 * 3 * DD,
                                  be_mid + 1 * 3 * DD, HI(7), LO(7), n);     // m1

    // ---- last ops ----
    k_agg<<<agg_grid, 256>>>(HI(6), LO(6), rowptr, ssrc, HI(1), LO(1), HI(2), LO(2), n);
    k_agg<<<agg_grid, 256>>>(HI(7), LO(7), rowptr, ssrc, HI(0), LO(0), HI(3), LO(3), n);
    gemm2(6, 1, 2, 7, 0, 3, 18, b_last, 6);
    k_combine2<<<ew_grid4, 256>>>(
        yb, ST(6), w_last + 0, g_lastP + 0 * 3 * DD, be_last + 0 * 3 * DD,
        yb + 3 * ystride, ST(7), w_last + 3, g_lastP + 1 * 3 * DD, be_last + 1 * 3 * DD,
        HI(8), LO(8), n);                                    // sl

    // ---- final: cat GEMM (3 K-chunks over m0,m1,sl planes) + column-norm ----
    k_gemm_mma<<<dim3(gtiles, 1, 1), 256, SMEM_MMA>>>(
        HI(6), LO(6), HI(7), LO(7), HI(8), LO(8),
        nullptr, nullptr, nullptr, nullptr, nullptr, nullptr,
        wpre + 24L * 16384, b_cat, yb, ST(8), n, ystride, 1);
    k_finalnorm<<<ew_grid, 256>>>(yb, ST(8), g_cat, be_cat, (float*)d_out, n);
}

// round 12
// speedup vs baseline: 1.0464x; 1.0464x over previous
#include <cuda_runtime.h>
#include <cuda_fp16.h>
#include <cstdint>
#include <math_constants.h>

#define NN 100000
#define EE 600000
#define DD 128
#define EPSLN 1e-5f
#define PLANE ((size_t)(NN + 128) * DD)   // padded hi/lo plane (tail rows read as 0)

// ---------------- scratch (device globals) -------------------------------------
__device__ float g_y[6L * NN * DD];          // 6 y planes (for z=6 batched GEMMs)
__device__ float g_statsA[9 * 2 * 3 * DD];   // 9 op slots x (sum, sumsq) x 3 x 128
__device__ int   g_deg[NN];
__device__ int   g_rowptr[NN + 1];
__device__ int   g_cursor[NN];
__device__ int   g_ssrc[EE];
__device__ int   g_bsums[256];
__device__ __half g_wpre[27L * 16384];       // per matrix: fp16 W^T [f*128+d]
// hi/lo candidate planes; slots: 0=pre0/aggB-mean 1=pre1/agg-mean 2=pre2/agg-max
//                                3=hin/aggB-max 4=s0 5=s1 6=m0 7=m1 8=sl
__device__ __half g_hlhi[9 * PLANE];
__device__ __half g_hllo[9 * PLANE];

// ---------------- helpers ------------------------------------------------------
__device__ __forceinline__ uint32_t smem_u32(const void* p) {
    uint32_t a;
    asm("{ .reg .u64 t; cvta.to.shared.u64 t, %1; cvt.u32.u64 %0, t; }" : "=r"(a) : "l"(p));
    return a;
}
__device__ __forceinline__ uint32_t pkh(__half a, __half b) {
    return (uint32_t)__half_as_ushort(a) | ((uint32_t)__half_as_ushort(b) << 16);
}
__device__ __forceinline__ void split4(float4 v, uint2& hi, uint2& lo) {
    __half h0 = __float2half_rn(v.x), h1 = __float2half_rn(v.y);
    __half h2 = __float2half_rn(v.z), h3 = __float2half_rn(v.w);
    __half l0 = __float2half_rn(v.x - __half2float(h0));
    __half l1 = __float2half_rn(v.y - __half2float(h1));
    __half l2 = __float2half_rn(v.z - __half2float(h2));
    __half l3 = __float2half_rn(v.w - __half2float(h3));
    hi = make_uint2(pkh(h0, h1), pkh(h2, h3));
    lo = make_uint2(pkh(l0, l1), pkh(l2, l3));
}
__device__ __forceinline__ float4 join4(uint2 hi, uint2 lo) {
    __half2 h01 = *(__half2*)&hi.x, h23 = *(__half2*)&hi.y;
    __half2 l01 = *(__half2*)&lo.x, l23 = *(__half2*)&lo.y;
    float2 a = __half22float2(h01), b = __half22float2(h23);
    float2 c = __half22float2(l01), d = __half22float2(l23);
    return make_float4(a.x + c.x, a.y + c.y, b.x + d.x, b.y + d.y);
}
__device__ __forceinline__ void ldsm_x4(uint32_t& r0, uint32_t& r1, uint32_t& r2, uint32_t& r3,
                                        uint32_t addr) {
    asm volatile("ldmatrix.sync.aligned.m8n8.x4.shared.b16 {%0, %1, %2, %3}, [%4];"
                 : "=r"(r0), "=r"(r1), "=r"(r2), "=r"(r3) : "r"(addr));
}
__device__ __forceinline__ void mma16816h(float* c, const uint32_t* a, const uint32_t* b) {
    asm volatile(
        "mma.sync.aligned.m16n8k16.row.col.f32.f16.f16.f32 "
        "{%0, %1, %2, %3}, {%4, %5, %6, %7}, {%8, %9}, {%0, %1, %2, %3};"
        : "+f"(c[0]), "+f"(c[1]), "+f"(c[2]), "+f"(c[3])
        : "r"(a[0]), "r"(a[1]), "r"(a[2]), "r"(a[3]), "r"(b[0]), "r"(b[1]));
}
__device__ __forceinline__ void cpasync16(uint32_t saddr, const void* gaddr) {
    asm volatile("cp.async.cg.shared.global [%0], [%1], 16;" :: "r"(saddr), "l"(gaddr));
}
__device__ __forceinline__ void cpasync_commit() {
    asm volatile("cp.async.commit_group;");
}
__device__ __forceinline__ void cpasync_wait0() {
    asm volatile("cp.async.wait_group 0;");
}

// ---------------- weight prep: W[d][f] fp32 -> fp16 W^T[f][d] -------------------
__global__ void k_wprep(const float* __restrict__ W, __half* __restrict__ out,
                        float* statszero, int zn) {
    if (statszero && blockIdx.x == 0) {
        for (int i = threadIdx.x; i < zn; i += blockDim.x) statszero[i] = 0.f;
    }
    int m = blockIdx.x >> 3;
    int part = blockIdx.x & 7;
    const float* src = W + (size_t)m * 16384;
    __half* oh = out + (size_t)m * 16384;
    int base = part * 2048;
    for (int i = threadIdx.x; i < 2048; i += blockDim.x) {
        int idx = base + i;
        int d = idx >> 7, f = idx & 127;
        oh[f * 128 + d] = __float2half_rn(src[idx]);
    }
}

// ---------------- zero-op candidates -> hi/lo planes ---------------------------
__global__ void k_pre_hl(const float* __restrict__ a, const float* __restrict__ b,
                         __half* h0, __half* l0, __half* h1, __half* l1,
                         __half* h2, __half* l2, int total4) {
    int i4 = blockIdx.x * blockDim.x + threadIdx.x;
    if (i4 >= total4) return;
    float4 x = ((const float4*)a)[i4];
    float4 y = ((const float4*)b)[i4];
    uint2 hi, lo;
    split4(x, hi, lo);
    ((uint2*)h0)[i4] = hi; ((uint2*)l0)[i4] = lo;
    float4 d = make_float4(x.x - y.x, x.y - y.y, x.z - y.z, x.w - y.w);
    split4(d, hi, lo);
    ((uint2*)h1)[i4] = hi; ((uint2*)l1)[i4] = lo;
    float4 p = make_float4(x.x * y.x, x.y * y.y, x.z * y.z, x.w * y.w);
    split4(p, hi, lo);
    ((uint2*)h2)[i4] = hi; ((uint2*)l2)[i4] = lo;
}

// ---------------- fp16 2-pass tensor GEMM, double-buffered swizzled fills -------
// Tiles are [128 rows x 64 halves] = 128B/row, XOR-16B swizzle (chunk ^= row&7).
#define TILE_BYTES 16384                     // 128 * 128B
#define BUFBYTES (3 * TILE_BYTES)            // Ahi+Alo+B per buffer set
#define SMEM_MMA (2 * BUFBYTES + 1024)

__global__ __launch_bounds__(256, 2) void k_gemm_mma(
    const __half* __restrict__ a0h, const __half* __restrict__ a0l,
    const __half* __restrict__ a1h, const __half* __restrict__ a1l,
    const __half* __restrict__ a2h, const __half* __restrict__ a2l,
    const __half* __restrict__ b0h, const __half* __restrict__ b0l,
    const __half* __restrict__ b1h, const __half* __restrict__ b1l,
    const __half* __restrict__ b2h, const __half* __restrict__ b2l,
    const __half* __restrict__ wpre, const float* __restrict__ bias,
    float* __restrict__ Y, float* __restrict__ stats, int n, size_t ystride, int catmode)
{
    extern __shared__ char sm[];
    float* ssum = (float*)(sm + 2 * BUFBYTES);
    float* ssq  = ssum + 128;

    int tid = threadIdx.x;
    int wid = tid >> 5, lane = tid & 31;
    int wm_ = wid >> 1, wn_ = wid & 1;
    int z = blockIdx.z;
    int opsel = z / 3;
    int kcand = catmode ? 0 : (z % 3);
    int nchunk = catmode ? 3 : 1;
    int row0 = blockIdx.x * 128;
    float* Yk = Y + (size_t)(opsel * 3 + kcand) * ystride;
    const float* bk = bias + (opsel * 3 + kcand) * DD;
    float* st = stats + opsel * 768;
    int so = kcand * DD;

    if (tid < 128) { ssum[tid] = 0.f; ssq[tid] = 0.f; }

    float c[2][8][4];
    #pragma unroll
    for (int i = 0; i < 2; i++)
        #pragma unroll
        for (int j = 0; j < 8; j++)
            #pragma unroll
            for (int q = 0; q < 4; q++) c[i][j][q] = 0.f;

    int a_row = wm_ * 32 + (lane & 15);
    int a_cs = lane >> 4;            // A chunk select (0/1)
    int b_f = wn_ * 64 + ((lane >> 4) << 3) + (lane & 7);
    int b_cs = (lane >> 3) & 1;      // B chunk select (0/1)
    uint32_t ubase = smem_u32(sm);

    // candidate plane tables
    const __half* XHt[3];
    const __half* XLt[3];
    if (opsel == 0 || catmode) {
        XHt[0] = a0h; XHt[1] = a1h; XHt[2] = a2h;
        XLt[0] = a0l; XLt[1] = a1l; XLt[2] = a2l;
    } else {
        XHt[0] = b0h; XHt[1] = b1h; XHt[2] = b2h;
        XLt[0] = b0l; XLt[1] = b1l; XLt[2] = b2l;
    }

    int totchunks = nchunk * 2;
    int frow = tid >> 1, fsg = tid & 1;   // fill mapping: 2 threads/row, 64B each per plane

    auto do_fill = [&](int tc, int buf) {
        int c3 = tc >> 1, ch = tc & 1;
        const __half* XH = catmode ? XHt[c3] : XHt[kcand];
        const __half* XL = catmode ? XLt[c3] : XLt[kcand];
        const __half* wmr = wpre + (size_t)(opsel * 3 + (catmode ? c3 : kcand)) * 16384;
        uint32_t bb = ubase + (uint32_t)(buf * BUFBYTES);
        size_t gofs = ((size_t)(row0 + frow) * DD + ch * 64) * 2 + fsg * 64;
        const char* sh = (const char*)XH + gofs;
        const char* sl = (const char*)XL + gofs;
        const char* sb = (const char*)wmr + ((size_t)frow * 128 + ch * 64) * 2 + fsg * 64;
        uint32_t rowbase = (uint32_t)(frow * 128);
        uint32_t rsw = (uint32_t)(frow & 7);
        #pragma unroll
        for (int q = 0; q < 4; q++) {
            uint32_t slot = (uint32_t)(((fsg * 4 + q) ^ rsw) << 4);
            cpasync16(bb + rowbase + slot, sh + q * 16);
            cpasync16(bb + TILE_BYTES + rowbase + slot, sl + q * 16);
            cpasync16(bb + 2 * TILE_BYTES + rowbase + slot, sb + q * 16);
        }
        cpasync_commit();
    };

    do_fill(0, 0);
    for (int tc = 0; tc < totchunks; tc++) {
        cpasync_wait0();
        __syncthreads();            // all warps done with previous mma; fill visible
        if (tc + 1 < totchunks) do_fill(tc + 1, (tc + 1) & 1);
        uint32_t bb = ubase + (uint32_t)((tc & 1) * BUFBYTES);
        uint32_t uAhi = bb;
        uint32_t uAlo = bb + TILE_BYTES;
        uint32_t uBh  = bb + 2 * TILE_BYTES;
        #pragma unroll
        for (int k = 0; k < 4; k++) {
            uint32_t ah[2][4], al[2][4];
            #pragma unroll
            for (int mt = 0; mt < 2; mt++) {
                int ra = a_row + mt * 16;
                uint32_t off = (uint32_t)(ra * 128 + (((2 * k + a_cs) ^ (ra & 7)) << 4));
                ldsm_x4(ah[mt][0], ah[mt][1], ah[mt][2], ah[mt][3], uAhi + off);
                ldsm_x4(al[mt][0], al[mt][1], al[mt][2], al[mt][3], uAlo + off);
            }
            uint32_t b[4][4];
            #pragma unroll
            for (int p = 0; p < 4; p++) {
                int rb = b_f + p * 16;
                uint32_t off = (uint32_t)(rb * 128 + (((2 * k + b_cs) ^ (rb & 7)) << 4));
                ldsm_x4(b[p][0], b[p][1], b[p][2], b[p][3], uBh + off);
            }
            #pragma unroll
            for (int mt = 0; mt < 2; mt++)
                #pragma unroll
                for (int nt = 0; nt < 8; nt++) {
                    mma16816h(c[mt][nt], ah[mt], &b[nt >> 1][(nt & 1) * 2]);
                    mma16816h(c[mt][nt], al[mt], &b[nt >> 1][(nt & 1) * 2]);
                }
        }
    }

    // ---------------- epilogue: bias, store Y, fused column stats ---------------
    int erow = lane >> 2, ecp = lane & 3;
    float2 bb2[8];
    #pragma unroll
    for (int nt = 0; nt < 8; nt++)
        bb2[nt] = *(const float2*)(bk + wn_ * 64 + nt * 8 + ecp * 2);

    float lsum[16], lsq[16];
    #pragma unroll
    for (int j = 0; j < 16; j++) { lsum[j] = 0.f; lsq[j] = 0.f; }

    #pragma unroll
    for (int mt = 0; mt < 2; mt++) {
        int r0g = row0 + wm_ * 32 + mt * 16 + erow;
        int r1g = r0g + 8;
        #pragma unroll
        for (int nt = 0; nt < 8; nt++) {
            int cbase = wn_ * 64 + nt * 8 + ecp * 2;
            float v00 = c[mt][nt][0] + bb2[nt].x;
            float v01 = c[mt][nt][1] + bb2[nt].y;
            float v10 = c[mt][nt][2] + bb2[nt].x;
            float v11 = c[mt][nt][3] + bb2[nt].y;
            if (r0g < n) {
                *(float2*)(Yk + (size_t)r0g * DD + cbase) = make_float2(v00, v01);
                lsum[nt * 2]     += v00; lsq[nt * 2]     += v00 * v00;
                lsum[nt * 2 + 1] += v01; lsq[nt * 2 + 1] += v01 * v01;
            }
            if (r1g < n) {
                *(float2*)(Yk + (size_t)r1g * DD + cbase) = make_float2(v10, v11);
                lsum[nt * 2]     += v10; lsq[nt * 2]     += v10 * v10;
                lsum[nt * 2 + 1] += v11; lsq[nt * 2 + 1] += v11 * v11;
            }
        }
    }
    #pragma unroll
    for (int nt = 0; nt < 8; nt++) {
        int cbase = wn_ * 64 + nt * 8 + ecp * 2;
        atomicAdd(&ssum[cbase],     lsum[nt * 2]);
        atomicAdd(&ssq[cbase],      lsq[nt * 2]);
        atomicAdd(&ssum[cbase + 1], lsum[nt * 2 + 1]);
        atomicAdd(&ssq[cbase + 1],  lsq[nt * 2 + 1]);
    }
    __syncthreads();
    if (tid < 128) {
        atomicAdd(&st[so + tid], ssum[tid]);
        atomicAdd(&st[3 * DD + so + tid], ssq[tid]);
    }
}

// ---------------- CSR build ---------------------------------------------------
__global__ void k_hist(const int* __restrict__ dst, int* deg, int e) {
    int i = blockIdx.x * blockDim.x + threadIdx.x;
    if (i < e) atomicAdd(&deg[dst[i]], 1);
}
__global__ void k_scan_block(const int* __restrict__ deg, int* incl, int* bsums, int n) {
    __shared__ int sh[1024];
    int i = blockIdx.x * 1024 + threadIdx.x;
    int v = (i < n) ? deg[i] : 0;
    sh[threadIdx.x] = v;
    __syncthreads();
    for (int off = 1; off < 1024; off <<= 1) {
        int t = (threadIdx.x >= off) ? sh[threadIdx.x - off] : 0;
        __syncthreads();
        sh[threadIdx.x] += t;
        __syncthreads();
    }
    if (i < n) incl[i] = sh[threadIdx.x];
    if (threadIdx.x == 1023) bsums[blockIdx.x] = sh[1023];
}
__global__ void k_scan_sums(int* bsums, int nb) {
    if (threadIdx.x == 0 && blockIdx.x == 0) {
        int run = 0;
        for (int i = 0; i < nb; i++) { int t = bsums[i]; bsums[i] = run; run += t; }
    }
}
__global__ void k_scan_fin(const int* __restrict__ deg, const int* __restrict__ incl,
                           const int* __restrict__ bsums, int* rowptr, int* cursor, int n, int e) {
    int i = blockIdx.x * blockDim.x + threadIdx.x;
    if (i < n) {
        int ex = incl[i] - deg[i] + bsums[i >> 10];
        rowptr[i] = ex;
        cursor[i] = ex;
        if (i == n - 1) rowptr[n] = e;
    }
}
__global__ void k_scatter(const int* __restrict__ src, const int* __restrict__ dst,
                          int* cursor, int* ssrc, int e) {
    int i = blockIdx.x * blockDim.x + threadIdx.x;
    if (i < e) {
        int p = atomicAdd(&cursor[dst[i]], 1);
        ssrc[p] = src[i];
    }
}

// ---------------- graph aggregation: planes in -> planes out, warp per node ----
__global__ void k_agg(const __half* __restrict__ hH, const __half* __restrict__ hL,
                      const int* __restrict__ rowptr, const int* __restrict__ ssrc,
                      __half* mhi, __half* mlo, __half* xhi, __half* xlo, int n) {
    int warp = (blockIdx.x * blockDim.x + threadIdx.x) >> 5;
    int lane = threadIdx.x & 31;
    if (warp >= n) return;
    int beg = rowptr[warp], end = rowptr[warp + 1];
    float4 s  = make_float4(0.f, 0.f, 0.f, 0.f);
    float4 mx = make_float4(-CUDART_INF_F, -CUDART_INF_F, -CUDART_INF_F, -CUDART_INF_F);
    for (int i = beg; i < end; i++) {
        int src = ssrc[i];
        uint2 hi = ((const uint2*)(hH + (size_t)src * DD))[lane];
        uint2 lo = ((const uint2*)(hL + (size_t)src * DD))[lane];
        float4 v = join4(hi, lo);
        s.x += v.x; s.y += v.y; s.z += v.z; s.w += v.w;
        mx.x = fmaxf(mx.x, v.x); mx.y = fmaxf(mx.y, v.y);
        mx.z = fmaxf(mx.z, v.z); mx.w = fmaxf(mx.w, v.w);
    }
    int deg = end - beg;
    float inv = 1.0f / (float)max(deg, 1);
    float4 mo = make_float4(s.x * inv, s.y * inv, s.z * inv, s.w * inv);
    float4 xo = (deg > 0) ? mx : make_float4(0.f, 0.f, 0.f, 0.f);
    uint2 hi, lo;
    split4(mo, hi, lo);
    ((uint2*)(mhi + (size_t)warp * DD))[lane] = hi;
    ((uint2*)(mlo + (size_t)warp * DD))[lane] = lo;
    split4(xo, hi, lo);
    ((uint2*)(xhi + (size_t)warp * DD))[lane] = hi;
    ((uint2*)(xlo + (size_t)warp * DD))[lane] = lo;
}

// ---------------- combine: normalize+relu+ksum -> hi/lo planes ------------------
__device__ __forceinline__ float4 mix3(const float* y, const float* stats,
                                       const float* wrow, const float* gg,
                                       const float* be, int i4, int d0, float fn,
                                       size_t plane_elts) {
    float4 acc = make_float4(0.f, 0.f, 0.f, 0.f);
    #pragma unroll
    for (int k = 0; k < 3; k++) {
        float wk = wrow[k];
        float4 v = ((const float4*)(y + (size_t)k * plane_elts))[i4];
        #pragma unroll
        for (int j = 0; j < 4; j++) {
            int d = d0 + j;
            float mu  = stats[k * DD + d] / fn;
            float var = stats[3 * DD + k * DD + d] / fn - mu * mu;
            float rs  = rsqrtf(var + EPSLN);
            float vv = (&v.x)[j];
            float t = (vv - mu) * rs * gg[k * DD + d] + be[k * DD + d];
            (&acc.x)[j] += wk * fmaxf(t, 0.f);
        }
    }
    return acc;
}

__global__ void k_combine1(const float* __restrict__ y, const float* __restrict__ stats,
                           const float* __restrict__ wrow, const float* __restrict__ gg,
                           const float* __restrict__ be,
                           __half* hiP, __half* loP, int n) {
    int i4 = blockIdx.x * blockDim.x + threadIdx.x;
    int total4 = (n * DD) >> 2;
    if (i4 >= total4) return;
    int d0 = (i4 << 2) & (DD - 1);
    float4 acc = mix3(y, stats, wrow, gg, be, i4, d0, (float)n, (size_t)n * DD);
    uint2 hi, lo;
    split4(acc, hi, lo);
    ((uint2*)hiP)[i4] = hi;
    ((uint2*)loP)[i4] = lo;
}

__global__ void k_combine2(const float* __restrict__ yA, const float* __restrict__ stA,
                           const float* __restrict__ wA, const float* __restrict__ gA,
                           const float* __restrict__ beA,
                           const float* __restrict__ yB, const float* __restrict__ stB,
                           const float* __restrict__ wB, const float* __restrict__ gB,
                           const float* __restrict__ beB,
                           __half* hiP, __half* loP, int n) {
    int i4 = blockIdx.x * blockDim.x + threadIdx.x;
    int total4 = (n * DD) >> 2;
    if (i4 >= total4) return;
    int d0 = (i4 << 2) & (DD - 1);
    float fn = (float)n;
    size_t pe = (size_t)n * DD;
    float4 a = mix3(yA, stA, wA, gA, beA, i4, d0, fn, pe);
    float4 b = mix3(yB, stB, wB, gB, beB, i4, d0, fn, pe);
    float4 acc = make_float4(a.x + b.x, a.y + b.y, a.z + b.z, a.w + b.w);
    uint2 hi, lo;
    split4(acc, hi, lo);
    ((uint2*)hiP)[i4] = hi;
    ((uint2*)loP)[i4] = lo;
}

// ---------------- final column-norm + relu ------------------------------------
__global__ void k_finalnorm(const float* __restrict__ h, const float* __restrict__ stats,
                            const float* __restrict__ gc, const float* __restrict__ bec,
                            float* __restrict__ out, int n) {
    int idx = blockIdx.x * blockDim.x + threadIdx.x;
    int total = n * DD;
    if (idx >= total) return;
    int d = idx & (DD - 1);
    float fn = (float)n;
    float mu  = stats[d] / fn;
    float var = stats[3 * DD + d] / fn - mu * mu;
    float rs  = rsqrtf(var + EPSLN);
    float v = (h[idx] - mu) * rs * gc[d] + bec[d];
    out[idx] = fmaxf(v, 0.f);
}

// ---------------- host orchestration ------------------------------------------
extern "C" void kernel_launch(void* const* d_in, const int* in_sizes, int n_in,
                              void* d_out, int out_size) {
    const float* src_emb = (const float*)d_in[0];
    const float* hr      = (const float*)d_in[1];
    const int*   esrc    = (const int*)d_in[2];
    const int*   edst    = (const int*)d_in[3];
    const float* w_zero  = (const float*)d_in[4];
    const float* w_first = (const float*)d_in[5];
    const float* w_mid   = (const float*)d_in[6];
    const float* w_last  = (const float*)d_in[7];
    const float* W_zero  = (const float*)d_in[8];
    const float* b_zero  = (const float*)d_in[9];
    const float* g_zeroP = (const float*)d_in[10];
    const float* be_zero = (const float*)d_in[11];
    const float* W_first = (const float*)d_in[12];
    const float* b_first = (const float*)d_in[13];
    const float* g_firstP= (const float*)d_in[14];
    const float* be_first= (const float*)d_in[15];
    const float* W_mid   = (const float*)d_in[16];
    const float* b_mid   = (const float*)d_in[17];
    const float* g_midP  = (const float*)d_in[18];
    const float* be_mid  = (const float*)d_in[19];
    const float* W_last  = (const float*)d_in[20];
    const float* b_last  = (const float*)d_in[21];
    const float* g_lastP = (const float*)d_in[22];
    const float* be_last = (const float*)d_in[23];
    const float* W_cat   = (const float*)d_in[24];
    const float* b_cat   = (const float*)d_in[25];
    const float* g_cat   = (const float*)d_in[26];
    const float* be_cat  = (const float*)d_in[27];

    int n = in_sizes[0] / DD;
    int e = in_sizes[2];

    float *yb, *statsA;
    int *deg, *rowptr, *cursor, *ssrc, *bsums;
    __half *wpre, *hlhi, *hllo;
    cudaGetSymbolAddress((void**)&yb, g_y);
    cudaGetSymbolAddress((void**)&statsA, g_statsA);
    cudaGetSymbolAddress((void**)&deg, g_deg);
    cudaGetSymbolAddress((void**)&rowptr, g_rowptr);
    cudaGetSymbolAddress((void**)&cursor, g_cursor);
    cudaGetSymbolAddress((void**)&ssrc, g_ssrc);
    cudaGetSymbolAddress((void**)&bsums, g_bsums);
    cudaGetSymbolAddress((void**)&wpre, g_wpre);
    cudaGetSymbolAddress((void**)&hlhi, g_hlhi);
    cudaGetSymbolAddress((void**)&hllo, g_hllo);

    cudaFuncSetAttribute(k_gemm_mma, cudaFuncAttributeMaxDynamicSharedMemorySize, SMEM_MMA);

    auto HI = [&](int s) { return hlhi + (size_t)s * PLANE; };
    auto LO = [&](int s) { return hllo + (size_t)s * PLANE; };
    auto ST = [&](int s) { return statsA + (size_t)s * 768; };

    int total = n * DD;
    size_t ystride = (size_t)n * DD;
    int gtiles = (n + 127) / 128;
    int ew_grid = (total + 255) / 256;
    int ew_grid4 = (total / 4 + 255) / 256;
    int agg_grid = (n + 7) / 8;
    int eb = (e + 255) / 256;
    int nb1024 = (n + 1023) / 1024;

    // ---- weight prep (stats slots zeroed in first launch) ----
    k_wprep<<<3 * 8, 256>>>(W_zero,  wpre + 0L  * 16384, statsA, 9 * 768);
    k_wprep<<<9 * 8, 256>>>(W_first, wpre + 3L  * 16384, nullptr, 0);
    k_wprep<<<6 * 8, 256>>>(W_mid,   wpre + 12L * 16384, nullptr, 0);
    k_wprep<<<6 * 8, 256>>>(W_last,  wpre + 18L * 16384, nullptr, 0);
    k_wprep<<<3 * 8, 256>>>(W_cat,   wpre + 24L * 16384, nullptr, 0);

    auto gemm1 = [&](int c0, int c1, int c2, int opmat, const float* B, int stslot) {
        k_gemm_mma<<<dim3(gtiles, 1, 3), 256, SMEM_MMA>>>(
            HI(c0), LO(c0), HI(c1), LO(c1), HI(c2), LO(c2),
            nullptr, nullptr, nullptr, nullptr, nullptr, nullptr,
            wpre + (size_t)opmat * 16384, B, yb, ST(stslot), n, ystride, 0);
    };
    auto gemm2 = [&](int a0, int a1, int a2, int b0, int b1, int b2,
                     int opmat, const float* B, int stslot) {
        k_gemm_mma<<<dim3(gtiles, 1, 6), 256, SMEM_MMA>>>(
            HI(a0), LO(a0), HI(a1), LO(a1), HI(a2), LO(a2),
            HI(b0), LO(b0), HI(b1), LO(b1), HI(b2), LO(b2),
            wpre + (size_t)opmat * 16384, B, yb, ST(stslot), n, ystride, 0);
    };

    // ---- zero op: pre candidates into slots 0,1,2; hin -> slot 3 ----
    k_pre_hl<<<ew_grid4, 256>>>(src_emb, hr, HI(0), LO(0), HI(1), LO(1), HI(2), LO(2), total / 4);
    gemm1(0, 1, 2, 0, b_zero, 0);

    // ---- CSR build ----
    cudaMemsetAsync(deg, 0, (size_t)n * sizeof(int));
    k_hist<<<eb, 256>>>(edst, deg, e);
    k_scan_block<<<nb1024, 1024>>>(deg, cursor, bsums, n);
    k_scan_sums<<<1, 32>>>(bsums, nb1024);
    k_scan_fin<<<(n + 255) / 256, 256>>>(deg, cursor, bsums, rowptr, cursor, n, e);
    k_scatter<<<eb, 256>>>(esrc, edst, cursor, ssrc, e);

    k_combine1<<<ew_grid4, 256>>>(yb, ST(0), w_zero, g_zeroP, be_zero, HI(3), LO(3), n);

    // ---- first ops ----
    k_agg<<<agg_grid, 256>>>(HI(3), LO(3), rowptr, ssrc, HI(1), LO(1), HI(2), LO(2), n);
    gemm2(3, 1, 2, 3, 1, 2, 3, b_first, 1);
    k_combine1<<<ew_grid4, 256>>>(yb, ST(1), w_first + 0, g_firstP + 0 * 3 * DD,
                                  be_first + 0 * 3 * DD, HI(4), LO(4), n);   // s0
    k_agg<<<agg_grid, 256>>>(HI(4), LO(4), rowptr, ssrc, HI(1), LO(1), HI(2), LO(2), n);
    gemm1(4, 1, 2, 9, b_first + 6 * DD, 3);
    k_combine2<<<ew_grid4, 256>>>(
        yb + 3 * ystride, ST(2), w_first + 3, g_firstP + 1 * 3 * DD, be_first + 1 * 3 * DD,
        yb, ST(3), w_first + 6, g_firstP + 2 * 3 * DD, be_first + 2 * 3 * DD,
        HI(5), LO(5), n);                                    // s1

    // ---- middle ops ---- (agg(s0) still in slots 1,2)
    gemm1(4, 1, 2, 12, b_mid, 4);
    k_combine1<<<ew_grid4, 256>>>(yb, ST(4), w_mid + 0, g_midP + 0 * 3 * DD,
                                  be_mid + 0 * 3 * DD, HI(6), LO(6), n);     // m0
    k_agg<<<agg_grid, 256>>>(HI(5), LO(5), rowptr, ssrc, HI(1), LO(1), HI(2), LO(2), n);
    gemm1(5, 1, 2, 15, b_mid + 3 * DD, 5);
    k_combine1<<<ew_grid4, 256>>>(yb, ST(5), w_mid + 3, g_midP + 1 * 3 * DD,
                                  be_mid + 1 * 3 * DD, HI(7), LO(7), n);     // m1

    // ---- last ops ----
    k_agg<<<agg_grid, 256>>>(HI(6), LO(6), rowptr, ssrc, HI(1), LO(1), HI(2), LO(2), n);
    k_agg<<<agg_grid, 256>>>(HI(7), LO(7), rowptr, ssrc, HI(0), LO(0), HI(3), LO(3), n);
    gemm2(6, 1, 2, 7, 0, 3, 18, b_last, 6);
    k_combine2<<<ew_grid4, 256>>>(
        yb, ST(6), w_last + 0, g_lastP + 0 * 3 * DD, be_last + 0 * 3 * DD,
        yb + 3 * ystride, ST(7), w_last + 3, g_lastP + 1 * 3 * DD, be_last + 1 * 3 * DD,
        HI(8), LO(8), n);                                    // sl

    // ---- final: cat GEMM (3 K-chunks over m0,m1,sl planes) + column-norm ----
    k_gemm_mma<<<dim3(gtiles, 1, 1), 256, SMEM_MMA>>>(
        HI(6), LO(6), HI(7), LO(7), HI(8), LO(8),
        nullptr, nullptr, nullptr, nullptr, nullptr, nullptr,
        wpre + 24L * 16384, b_cat, yb, ST(8), n, ystride, 1);
    k_finalnorm<<<ew_grid, 256>>>(yb, ST(8), g_cat, be_cat, (float*)d_out, n);
}

// round 13
// speedup vs baseline: 1.0691x; 1.0216x over previous
#include <cuda_runtime.h>
#include <cuda_fp16.h>
#include <cstdint>
#include <math_constants.h>

#define NN 100000
#define EE 600000
#define DD 128
#define EPSLN 1e-5f
#define PLANE ((size_t)(NN + 128) * DD)   // padded hi/lo plane (tail rows read as 0)

// ---------------- scratch (device globals) -------------------------------------
__device__ float g_y[6L * NN * DD];
__device__ float g_statsA[9 * 2 * 3 * DD];
__device__ int   g_deg[NN];
__device__ int   g_rowptr[NN + 1];
__device__ int   g_cursor[NN];
__device__ int   g_ssrc[EE];
__device__ int   g_bsums[256];
__device__ __half g_wpre[27L * 16384];
__device__ __half g_hlhi[9 * PLANE];
__device__ __half g_hllo[9 * PLANE];

// ---------------- helpers ------------------------------------------------------
__device__ __forceinline__ uint32_t smem_u32(const void* p) {
    uint32_t a;
    asm("{ .reg .u64 t; cvta.to.shared.u64 t, %1; cvt.u32.u64 %0, t; }" : "=r"(a) : "l"(p));
    return a;
}
__device__ __forceinline__ uint32_t pkh(__half a, __half b) {
    return (uint32_t)__half_as_ushort(a) | ((uint32_t)__half_as_ushort(b) << 16);
}
__device__ __forceinline__ void split4(float4 v, uint2& hi, uint2& lo) {
    __half h0 = __float2half_rn(v.x), h1 = __float2half_rn(v.y);
    __half h2 = __float2half_rn(v.z), h3 = __float2half_rn(v.w);
    __half l0 = __float2half_rn(v.x - __half2float(h0));
    __half l1 = __float2half_rn(v.y - __half2float(h1));
    __half l2 = __float2half_rn(v.z - __half2float(h2));
    __half l3 = __float2half_rn(v.w - __half2float(h3));
    hi = make_uint2(pkh(h0, h1), pkh(h2, h3));
    lo = make_uint2(pkh(l0, l1), pkh(l2, l3));
}
__device__ __forceinline__ float4 join4(uint2 hi, uint2 lo) {
    __half2 h01 = *(__half2*)&hi.x, h23 = *(__half2*)&hi.y;
    __half2 l01 = *(__half2*)&lo.x, l23 = *(__half2*)&lo.y;
    float2 a = __half22float2(h01), b = __half22float2(h23);
    float2 c = __half22float2(l01), d = __half22float2(l23);
    return make_float4(a.x + c.x, a.y + c.y, b.x + d.x, b.y + d.y);
}
__device__ __forceinline__ void ldsm_x4(uint32_t& r0, uint32_t& r1, uint32_t& r2, uint32_t& r3,
                                        uint32_t addr) {
    asm volatile("ldmatrix.sync.aligned.m8n8.x4.shared.b16 {%0, %1, %2, %3}, [%4];"
                 : "=r"(r0), "=r"(r1), "=r"(r2), "=r"(r3) : "r"(addr));
}
__device__ __forceinline__ void mma16816h(float* c, const uint32_t* a, const uint32_t* b) {
    asm volatile(
        "mma.sync.aligned.m16n8k16.row.col.f32.f16.f16.f32 "
        "{%0, %1, %2, %3}, {%4, %5, %6, %7}, {%8, %9}, {%0, %1, %2, %3};"
        : "+f"(c[0]), "+f"(c[1]), "+f"(c[2]), "+f"(c[3])
        : "r"(a[0]), "r"(a[1]), "r"(a[2]), "r"(a[3]), "r"(b[0]), "r"(b[1]));
}
__device__ __forceinline__ void cpasync16(uint32_t saddr, const void* gaddr) {
    asm volatile("cp.async.cg.shared.global [%0], [%1], 16;" :: "r"(saddr), "l"(gaddr));
}
__device__ __forceinline__ void cpasync_commit() {
    asm volatile("cp.async.commit_group;");
}
__device__ __forceinline__ void cpasync_wait0() {
    asm volatile("cp.async.wait_group 0;");
}

// ---------------- weight prep ---------------------------------------------------
__global__ void k_wprep(const float* __restrict__ W, __half* __restrict__ out,
                        float* statszero, int zn) {
    if (statszero && blockIdx.x == 0) {
        for (int i = threadIdx.x; i < zn; i += blockDim.x) statszero[i] = 0.f;
    }
    int m = blockIdx.x >> 3;
    int part = blockIdx.x & 7;
    const float* src = W + (size_t)m * 16384;
    __half* oh = out + (size_t)m * 16384;
    int base = part * 2048;
    for (int i = threadIdx.x; i < 2048; i += blockDim.x) {
        int idx = base + i;
        int d = idx >> 7, f = idx & 127;
        oh[f * 128 + d] = __float2half_rn(src[idx]);
    }
}

// ---------------- zero-op candidates -> hi/lo planes ---------------------------
__global__ void k_pre_hl(const float* __restrict__ a, const float* __restrict__ b,
                         __half* h0, __half* l0, __half* h1, __half* l1,
                         __half* h2, __half* l2, int total4) {
    int i4 = blockIdx.x * blockDim.x + threadIdx.x;
    if (i4 >= total4) return;
    float4 x = ((const float4*)a)[i4];
    float4 y = ((const float4*)b)[i4];
    uint2 hi, lo;
    split4(x, hi, lo);
    ((uint2*)h0)[i4] = hi; ((uint2*)l0)[i4] = lo;
    float4 d = make_float4(x.x - y.x, x.y - y.y, x.z - y.z, x.w - y.w);
    split4(d, hi, lo);
    ((uint2*)h1)[i4] = hi; ((uint2*)l1)[i4] = lo;
    float4 p = make_float4(x.x * y.x, x.y * y.y, x.z * y.z, x.w * y.w);
    split4(p, hi, lo);
    ((uint2*)h2)[i4] = hi; ((uint2*)l2)[i4] = lo;
}

// ---------------- fp16 2-pass tensor GEMM, double-buffered swizzled fills -------
#define TILE_BYTES 16384
#define BUFBYTES (3 * TILE_BYTES)
#define SMEM_MMA (2 * BUFBYTES + 1024)

__global__ __launch_bounds__(256, 2) void k_gemm_mma(
    const __half* __restrict__ a0h, const __half* __restrict__ a0l,
    const __half* __restrict__ a1h, const __half* __restrict__ a1l,
    const __half* __restrict__ a2h, const __half* __restrict__ a2l,
    const __half* __restrict__ b0h, const __half* __restrict__ b0l,
    const __half* __restrict__ b1h, const __half* __restrict__ b1l,
    const __half* __restrict__ b2h, const __half* __restrict__ b2l,
    const __half* __restrict__ wpre, const float* __restrict__ bias,
    float* __restrict__ Y, float* __restrict__ stats, int n, size_t ystride, int catmode)
{
    extern __shared__ char sm[];
    float* ssum = (float*)(sm + 2 * BUFBYTES);
    float* ssq  = ssum + 128;

    int tid = threadIdx.x;
    int wid = tid >> 5, lane = tid & 31;
    int wm_ = wid >> 1, wn_ = wid & 1;
    int z = blockIdx.z;
    int opsel = z / 3;
    int kcand = catmode ? 0 : (z % 3);
    int nchunk = catmode ? 3 : 1;
    int row0 = blockIdx.x * 128;
    float* Yk = Y + (size_t)(opsel * 3 + kcand) * ystride;
    const float* bk = bias + (opsel * 3 + kcand) * DD;
    float* st = stats + opsel * 768;
    int so = kcand * DD;

    if (tid < 128) { ssum[tid] = 0.f; ssq[tid] = 0.f; }

    float c[2][8][4];
    #pragma unroll
    for (int i = 0; i < 2; i++)
        #pragma unroll
        for (int j = 0; j < 8; j++)
            #pragma unroll
            for (int q = 0; q < 4; q++) c[i][j][q] = 0.f;

    int a_row = wm_ * 32 + (lane & 15);
    int a_cs = lane >> 4;
    int b_f = wn_ * 64 + ((lane >> 4) << 3) + (lane & 7);
    int b_cs = (lane >> 3) & 1;
    uint32_t ubase = smem_u32(sm);

    const __half* XHt[3];
    const __half* XLt[3];
    if (opsel == 0 || catmode) {
        XHt[0] = a0h; XHt[1] = a1h; XHt[2] = a2h;
        XLt[0] = a0l; XLt[1] = a1l; XLt[2] = a2l;
    } else {
        XHt[0] = b0h; XHt[1] = b1h; XHt[2] = b2h;
        XLt[0] = b0l; XLt[1] = b1l; XLt[2] = b2l;
    }

    int totchunks = nchunk * 2;
    int frow = tid >> 1, fsg = tid & 1;

    auto do_fill = [&](int tc, int buf) {
        int c3 = tc >> 1, ch = tc & 1;
        const __half* XH = catmode ? XHt[c3] : XHt[kcand];
        const __half* XL = catmode ? XLt[c3] : XLt[kcand];
        const __half* wmr = wpre + (size_t)(opsel * 3 + (catmode ? c3 : kcand)) * 16384;
        uint32_t bb = ubase + (uint32_t)(buf * BUFBYTES);
        size_t gofs = ((size_t)(row0 + frow) * DD + ch * 64) * 2 + fsg * 64;
        const char* sh = (const char*)XH + gofs;
        const char* sl = (const char*)XL + gofs;
        const char* sb = (const char*)wmr + ((size_t)frow * 128 + ch * 64) * 2 + fsg * 64;
        uint32_t rowbase = (uint32_t)(frow * 128);
        uint32_t rsw = (uint32_t)(frow & 7);
        #pragma unroll
        for (int q = 0; q < 4; q++) {
            uint32_t slot = (uint32_t)(((fsg * 4 + q) ^ rsw) << 4);
            cpasync16(bb + rowbase + slot, sh + q * 16);
            cpasync16(bb + TILE_BYTES + rowbase + slot, sl + q * 16);
            cpasync16(bb + 2 * TILE_BYTES + rowbase + slot, sb + q * 16);
        }
        cpasync_commit();
    };

    do_fill(0, 0);
    for (int tc = 0; tc < totchunks; tc++) {
        cpasync_wait0();
        __syncthreads();
        if (tc + 1 < totchunks) do_fill(tc + 1, (tc + 1) & 1);
        uint32_t bb = ubase + (uint32_t)((tc & 1) * BUFBYTES);
        uint32_t uAhi = bb;
        uint32_t uAlo = bb + TILE_BYTES;
        uint32_t uBh  = bb + 2 * TILE_BYTES;
        #pragma unroll
        for (int k = 0; k < 4; k++) {
            uint32_t ah[2][4], al[2][4];
            #pragma unroll
            for (int mt = 0; mt < 2; mt++) {
                int ra = a_row + mt * 16;
                uint32_t off = (uint32_t)(ra * 128 + (((2 * k + a_cs) ^ (ra & 7)) << 4));
                ldsm_x4(ah[mt][0], ah[mt][1], ah[mt][2], ah[mt][3], uAhi + off);
                ldsm_x4(al[mt][0], al[mt][1], al[mt][2], al[mt][3], uAlo + off);
            }
            uint32_t b[4][4];
            #pragma unroll
            for (int p = 0; p < 4; p++) {
                int rb = b_f + p * 16;
                uint32_t off = (uint32_t)(rb * 128 + (((2 * k + b_cs) ^ (rb & 7)) << 4));
                ldsm_x4(b[p][0], b[p][1], b[p][2], b[p][3], uBh + off);
            }
            #pragma unroll
            for (int mt = 0; mt < 2; mt++)
                #pragma unroll
                for (int nt = 0; nt < 8; nt++) {
                    mma16816h(c[mt][nt], ah[mt], &b[nt >> 1][(nt & 1) * 2]);
                    mma16816h(c[mt][nt], al[mt], &b[nt >> 1][(nt & 1) * 2]);
                }
        }
    }

    int erow = lane >> 2, ecp = lane & 3;
    float2 bb2[8];
    #pragma unroll
    for (int nt = 0; nt < 8; nt++)
        bb2[nt] = *(const float2*)(bk + wn_ * 64 + nt * 8 + ecp * 2);

    float lsum[16], lsq[16];
    #pragma unroll
    for (int j = 0; j < 16; j++) { lsum[j] = 0.f; lsq[j] = 0.f; }

    #pragma unroll
    for (int mt = 0; mt < 2; mt++) {
        int r0g = row0 + wm_ * 32 + mt * 16 + erow;
        int r1g = r0g + 8;
        #pragma unroll
        for (int nt = 0; nt < 8; nt++) {
            int cbase = wn_ * 64 + nt * 8 + ecp * 2;
            float v00 = c[mt][nt][0] + bb2[nt].x;
            float v01 = c[mt][nt][1] + bb2[nt].y;
            float v10 = c[mt][nt][2] + bb2[nt].x;
            float v11 = c[mt][nt][3] + bb2[nt].y;
            if (r0g < n) {
                *(float2*)(Yk + (size_t)r0g * DD + cbase) = make_float2(v00, v01);
                lsum[nt * 2]     += v00; lsq[nt * 2]     += v00 * v00;
                lsum[nt * 2 + 1] += v01; lsq[nt * 2 + 1] += v01 * v01;
            }
            if (r1g < n) {
                *(float2*)(Yk + (size_t)r1g * DD + cbase) = make_float2(v10, v11);
                lsum[nt * 2]     += v10; lsq[nt * 2]     += v10 * v10;
                lsum[nt * 2 + 1] += v11; lsq[nt * 2 + 1] += v11 * v11;
            }
        }
    }
    #pragma unroll
    for (int nt = 0; nt < 8; nt++) {
        int cbase = wn_ * 64 + nt * 8 + ecp * 2;
        atomicAdd(&ssum[cbase],     lsum[nt * 2]);
        atomicAdd(&ssq[cbase],      lsq[nt * 2]);
        atomicAdd(&ssum[cbase + 1], lsum[nt * 2 + 1]);
        atomicAdd(&ssq[cbase + 1],  lsq[nt * 2 + 1]);
    }
    __syncthreads();
    if (tid < 128) {
        atomicAdd(&st[so + tid], ssum[tid]);
        atomicAdd(&st[3 * DD + so + tid], ssq[tid]);
    }
}

// ---------------- CSR build ---------------------------------------------------
__global__ void k_hist(const int* __restrict__ dst, int* deg, int e) {
    int i = blockIdx.x * blockDim.x + threadIdx.x;
    if (i < e) atomicAdd(&deg[dst[i]], 1);
}
__global__ void k_scan_block(const int* __restrict__ deg, int* incl, int* bsums, int n) {
    __shared__ int sh[1024];
    int i = blockIdx.x * 1024 + threadIdx.x;
    int v = (i < n) ? deg[i] : 0;
    sh[threadIdx.x] = v;
    __syncthreads();
    for (int off = 1; off < 1024; off <<= 1) {
        int t = (threadIdx.x >= off) ? sh[threadIdx.x - off] : 0;
        __syncthreads();
        sh[threadIdx.x] += t;
        __syncthreads();
    }
    if (i < n) incl[i] = sh[threadIdx.x];
    if (threadIdx.x == 1023) bsums[blockIdx.x] = sh[1023];
}
__global__ void k_scan_sums(int* bsums, int nb) {
    if (threadIdx.x == 0 && blockIdx.x == 0) {
        int run = 0;
        for (int i = 0; i < nb; i++) { int t = bsums[i]; bsums[i] = run; run += t; }
    }
}
__global__ void k_scan_fin(const int* __restrict__ deg, const int* __restrict__ incl,
                           const int* __restrict__ bsums, int* rowptr, int* cursor, int n, int e) {
    int i = blockIdx.x * blockDim.x + threadIdx.x;
    if (i < n) {
        int ex = incl[i] - deg[i] + bsums[i >> 10];
        rowptr[i] = ex;
        cursor[i] = ex;
        if (i == n - 1) rowptr[n] = e;
    }
}
__global__ void k_scatter(const int* __restrict__ src, const int* __restrict__ dst,
                          int* cursor, int* ssrc, int e) {
    int i = blockIdx.x * blockDim.x + threadIdx.x;
    if (i < e) {
        int p = atomicAdd(&cursor[dst[i]], 1);
        ssrc[p] = src[i];
    }
}

// ---------------- graph aggregation: planes in -> planes out -------------------
__global__ void k_agg(const __half* __restrict__ hH, const __half* __restrict__ hL,
                      const int* __restrict__ rowptr, const int* __restrict__ ssrc,
                      __half* mhi, __half* mlo, __half* xhi, __half* xlo, int n) {
    int warp = (blockIdx.x * blockDim.x + threadIdx.x) >> 5;
    int lane = threadIdx.x & 31;
    if (warp >= n) return;
    int beg = rowptr[warp], end = rowptr[warp + 1];
    float4 s  = make_float4(0.f, 0.f, 0.f, 0.f);
    float4 mx = make_float4(-CUDART_INF_F, -CUDART_INF_F, -CUDART_INF_F, -CUDART_INF_F);
    for (int i = beg; i < end; i++) {
        int src = ssrc[i];
        uint2 hi = ((const uint2*)(hH + (size_t)src * DD))[lane];
        uint2 lo = ((const uint2*)(hL + (size_t)src * DD))[lane];
        float4 v = join4(hi, lo);
        s.x += v.x; s.y += v.y; s.z += v.z; s.w += v.w;
        mx.x = fmaxf(mx.x, v.x); mx.y = fmaxf(mx.y, v.y);
        mx.z = fmaxf(mx.z, v.z); mx.w = fmaxf(mx.w, v.w);
    }
    int deg = end - beg;
    float inv = 1.0f / (float)max(deg, 1);
    float4 mo = make_float4(s.x * inv, s.y * inv, s.z * inv, s.w * inv);
    float4 xo = (deg > 0) ? mx : make_float4(0.f, 0.f, 0.f, 0.f);
    uint2 hi, lo;
    split4(mo, hi, lo);
    ((uint2*)(mhi + (size_t)warp * DD))[lane] = hi;
    ((uint2*)(mlo + (size_t)warp * DD))[lane] = lo;
    split4(xo, hi, lo);
    ((uint2*)(xhi + (size_t)warp * DD))[lane] = hi;
    ((uint2*)(xlo + (size_t)warp * DD))[lane] = lo;
}

// ---------------- combine: normalize+relu+ksum -> hi/lo planes ------------------
__device__ __forceinline__ float4 mix3(const float* y, const float* stats,
                                       const float* wrow, const float* gg,
                                       const float* be, int i4, int d0, float fn,
                                       size_t plane_elts) {
    float4 acc = make_float4(0.f, 0.f, 0.f, 0.f);
    #pragma unroll
    for (int k = 0; k < 3; k++) {
        float wk = wrow[k];
        float4 v = ((const float4*)(y + (size_t)k * plane_elts))[i4];
        #pragma unroll
        for (int j = 0; j < 4; j++) {
            int d = d0 + j;
            float mu  = stats[k * DD + d] / fn;
            float var = stats[3 * DD + k * DD + d] / fn - mu * mu;
            float rs  = rsqrtf(var + EPSLN);
            float vv = (&v.x)[j];
            float t = (vv - mu) * rs * gg[k * DD + d] + be[k * DD + d];
            (&acc.x)[j] += wk * fmaxf(t, 0.f);
        }
    }
    return acc;
}

__global__ void k_combine1(const float* __restrict__ y, const float* __restrict__ stats,
                           const float* __restrict__ wrow, const float* __restrict__ gg,
                           const float* __restrict__ be,
                           __half* hiP, __half* loP, int n) {
    int i4 = blockIdx.x * blockDim.x + threadIdx.x;
    int total4 = (n * DD) >> 2;
    if (i4 >= total4) return;
    int d0 = (i4 << 2) & (DD - 1);
    float4 acc = mix3(y, stats, wrow, gg, be, i4, d0, (float)n, (size_t)n * DD);
    uint2 hi, lo;
    split4(acc, hi, lo);
    ((uint2*)hiP)[i4] = hi;
    ((uint2*)loP)[i4] = lo;
}

__global__ void k_combine2(const float* __restrict__ yA, const float* __restrict__ stA,
                           const float* __restrict__ wA, const float* __restrict__ gA,
                           const float* __restrict__ beA,
                           const float* __restrict__ yB, const float* __restrict__ stB,
                           const float* __restrict__ wB, const float* __restrict__ gB,
                           const float* __restrict__ beB,
                           __half* hiP, __half* loP, int n) {
    int i4 = blockIdx.x * blockDim.x + threadIdx.x;
    int total4 = (n * DD) >> 2;
    if (i4 >= total4) return;
    int d0 = (i4 << 2) & (DD - 1);
    float fn = (float)n;
    size_t pe = (size_t)n * DD;
    float4 a = mix3(yA, stA, wA, gA, beA, i4, d0, fn, pe);
    float4 b = mix3(yB, stB, wB, gB, beB, i4, d0, fn, pe);
    float4 acc = make_float4(a.x + b.x, a.y + b.y, a.z + b.z, a.w + b.w);
    uint2 hi, lo;
    split4(acc, hi, lo);
    ((uint2*)hiP)[i4] = hi;
    ((uint2*)loP)[i4] = lo;
}

// ---------------- final column-norm + relu ------------------------------------
__global__ void k_finalnorm(const float* __restrict__ h, const float* __restrict__ stats,
                            const float* __restrict__ gc, const float* __restrict__ bec,
                            float* __restrict__ out, int n) {
    int idx = blockIdx.x * blockDim.x + threadIdx.x;
    int total = n * DD;
    if (idx >= total) return;
    int d = idx & (DD - 1);
    float fn = (float)n;
    float mu  = stats[d] / fn;
    float var = stats[3 * DD + d] / fn - mu * mu;
    float rs  = rsqrtf(var + EPSLN);
    float v = (h[idx] - mu) * rs * gc[d] + bec[d];
    out[idx] = fmaxf(v, 0.f);
}

// ---------------- host orchestration (multi-stream fork/join) -------------------
extern "C" void kernel_launch(void* const* d_in, const int* in_sizes, int n_in,
                              void* d_out, int out_size) {
    const float* src_emb = (const float*)d_in[0];
    const float* hr      = (const float*)d_in[1];
    const int*   esrc    = (const int*)d_in[2];
    const int*   edst    = (const int*)d_in[3];
    const float* w_zero  = (const float*)d_in[4];
    const float* w_first = (const float*)d_in[5];
    const float* w_mid   = (const float*)d_in[6];
    const float* w_last  = (const float*)d_in[7];
    const float* W_zero  = (const float*)d_in[8];
    const float* b_zero  = (const float*)d_in[9];
    const float* g_zeroP = (const float*)d_in[10];
    const float* be_zero = (const float*)d_in[11];
    const float* W_first = (const float*)d_in[12];
    const float* b_first = (const float*)d_in[13];
    const float* g_firstP= (const float*)d_in[14];
    const float* be_first= (const float*)d_in[15];
    const float* W_mid   = (const float*)d_in[16];
    const float* b_mid   = (const float*)d_in[17];
    const float* g_midP  = (const float*)d_in[18];
    const float* be_mid  = (const float*)d_in[19];
    const float* W_last  = (const float*)d_in[20];
    const float* b_last  = (const float*)d_in[21];
    const float* g_lastP = (const float*)d_in[22];
    const float* be_last = (const float*)d_in[23];
    const float* W_cat   = (const float*)d_in[24];
    const float* b_cat   = (const float*)d_in[25];
    const float* g_cat   = (const float*)d_in[26];
    const float* be_cat  = (const float*)d_in[27];

    int n = in_sizes[0] / DD;
    int e = in_sizes[2];

    float *yb, *statsA;
    int *deg, *rowptr, *cursor, *ssrc, *bsums;
    __half *wpre, *hlhi, *hllo;
    cudaGetSymbolAddress((void**)&yb, g_y);
    cudaGetSymbolAddress((void**)&statsA, g_statsA);
    cudaGetSymbolAddress((void**)&deg, g_deg);
    cudaGetSymbolAddress((void**)&rowptr, g_rowptr);
    cudaGetSymbolAddress((void**)&cursor, g_cursor);
    cudaGetSymbolAddress((void**)&ssrc, g_ssrc);
    cudaGetSymbolAddress((void**)&bsums, g_bsums);
    cudaGetSymbolAddress((void**)&wpre, g_wpre);
    cudaGetSymbolAddress((void**)&hlhi, g_hlhi);
    cudaGetSymbolAddress((void**)&hllo, g_hllo);

    // persistent side streams / events (created once, outside capture)
    static cudaStream_t sA = nullptr, sB = nullptr;
    static cudaEvent_t evFork, evWprep, evCsr, evS1, evAggS1, evM0, evAggM0;
    if (!sA) {
        cudaStreamCreateWithFlags(&sA, cudaStreamNonBlocking);
        cudaStreamCreateWithFlags(&sB, cudaStreamNonBlocking);
        cudaEventCreateWithFlags(&evFork, cudaEventDisableTiming);
        cudaEventCreateWithFlags(&evWprep, cudaEventDisableTiming);
        cudaEventCreateWithFlags(&evCsr, cudaEventDisableTiming);
        cudaEventCreateWithFlags(&evS1, cudaEventDisableTiming);
        cudaEventCreateWithFlags(&evAggS1, cudaEventDisableTiming);
        cudaEventCreateWithFlags(&evM0, cudaEventDisableTiming);
        cudaEventCreateWithFlags(&evAggM0, cudaEventDisableTiming);
        cudaFuncSetAttribute(k_gemm_mma, cudaFuncAttributeMaxDynamicSharedMemorySize, SMEM_MMA);
    }

    auto HI = [&](int s) { return hlhi + (size_t)s * PLANE; };
    auto LO = [&](int s) { return hllo + (size_t)s * PLANE; };
    auto ST = [&](int s) { return statsA + (size_t)s * 768; };

    int total = n * DD;
    size_t ystride = (size_t)n * DD;
    int gtiles = (n + 127) / 128;
    int ew_grid = (total + 255) / 256;
    int ew_grid4 = (total / 4 + 255) / 256;
    int agg_grid = (n + 7) / 8;
    int eb = (e + 255) / 256;
    int nb1024 = (n + 1023) / 1024;

    auto gemm1 = [&](int c0, int c1, int c2, int opmat, const float* B, int stslot) {
        k_gemm_mma<<<dim3(gtiles, 1, 3), 256, SMEM_MMA>>>(
            HI(c0), LO(c0), HI(c1), LO(c1), HI(c2), LO(c2),
            nullptr, nullptr, nullptr, nullptr, nullptr, nullptr,
            wpre + (size_t)opmat * 16384, B, yb, ST(stslot), n, ystride, 0);
    };
    auto gemm2 = [&](int a0, int a1, int a2, int b0, int b1, int b2,
                     int opmat, const float* B, int stslot) {
        k_gemm_mma<<<dim3(gtiles, 1, 6), 256, SMEM_MMA>>>(
            HI(a0), LO(a0), HI(a1), LO(a1), HI(a2), LO(a2),
            HI(b0), LO(b0), HI(b1), LO(b1), HI(b2), LO(b2),
            wpre + (size_t)opmat * 16384, B, yb, ST(stslot), n, ystride, 0);
    };

    // ---- fork point ----
    cudaEventRecord(evFork, 0);

    // side A: remaining weight preps
    cudaStreamWaitEvent(sA, evFork, 0);
    k_wprep<<<9 * 8, 256, 0, sA>>>(W_first, wpre + 3L  * 16384, nullptr, 0);
    k_wprep<<<6 * 8, 256, 0, sA>>>(W_mid,   wpre + 12L * 16384, nullptr, 0);
    k_wprep<<<6 * 8, 256, 0, sA>>>(W_last,  wpre + 18L * 16384, nullptr, 0);
    k_wprep<<<3 * 8, 256, 0, sA>>>(W_cat,   wpre + 24L * 16384, nullptr, 0);
    cudaEventRecord(evWprep, sA);

    // side B: CSR build
    cudaStreamWaitEvent(sB, evFork, 0);
    cudaMemsetAsync(deg, 0, (size_t)n * sizeof(int), sB);
    k_hist<<<eb, 256, 0, sB>>>(edst, deg, e);
    k_scan_block<<<nb1024, 1024, 0, sB>>>(deg, cursor, bsums, n);
    k_scan_sums<<<1, 32, 0, sB>>>(bsums, nb1024);
    k_scan_fin<<<(n + 255) / 256, 256, 0, sB>>>(deg, cursor, bsums, rowptr, cursor, n, e);
    k_scatter<<<eb, 256, 0, sB>>>(esrc, edst, cursor, ssrc, e);
    cudaEventRecord(evCsr, sB);

    // main: zero op
    k_wprep<<<3 * 8, 256>>>(W_zero, wpre + 0L * 16384, statsA, 9 * 768);
    k_pre_hl<<<ew_grid4, 256>>>(src_emb, hr, HI(0), LO(0), HI(1), LO(1), HI(2), LO(2), total / 4);
    gemm1(0, 1, 2, 0, b_zero, 0);
    k_combine1<<<ew_grid4, 256>>>(yb, ST(0), w_zero, g_zeroP, be_zero, HI(3), LO(3), n);

    // ---- first ops ----
    cudaStreamWaitEvent(0, evCsr, 0);
    k_agg<<<agg_grid, 256>>>(HI(3), LO(3), rowptr, ssrc, HI(1), LO(1), HI(2), LO(2), n);
    cudaStreamWaitEvent(0, evWprep, 0);
    gemm2(3, 1, 2, 3, 1, 2, 3, b_first, 1);
    k_combine1<<<ew_grid4, 256>>>(yb, ST(1), w_first + 0, g_firstP + 0 * 3 * DD,
                                  be_first + 0 * 3 * DD, HI(4), LO(4), n);   // s0
    k_agg<<<agg_grid, 256>>>(HI(4), LO(4), rowptr, ssrc, HI(1), LO(1), HI(2), LO(2), n);
    gemm1(4, 1, 2, 9, b_first + 6 * DD, 3);
    k_combine2<<<ew_grid4, 256>>>(
        yb + 3 * ystride, ST(2), w_first + 3, g_firstP + 1 * 3 * DD, be_first + 1 * 3 * DD,
        yb, ST(3), w_first + 6, g_firstP + 2 * 3 * DD, be_first + 2 * 3 * DD,
        HI(5), LO(5), n);                                    // s1
    cudaEventRecord(evS1, 0);

    // side A: agg(s1) -> slots 0(mean),3(max)   (parallel with mid0 chain)
    cudaStreamWaitEvent(sA, evS1, 0);
    k_agg<<<agg_grid, 256, 0, sA>>>(HI(5), LO(5), rowptr, ssrc, HI(0), LO(0), HI(3), LO(3), n);
    cudaEventRecord(evAggS1, sA);

    // main: mid0 (uses agg(s0) in slots 1,2)
    gemm1(4, 1, 2, 12, b_mid, 4);
    k_combine1<<<ew_grid4, 256>>>(yb, ST(4), w_mid + 0, g_midP + 0 * 3 * DD,
                                  be_mid + 0 * 3 * DD, HI(6), LO(6), n);     // m0
    cudaEventRecord(evM0, 0);

    // side B: agg(m0) -> slots 1,2   (parallel with mid1 chain)
    cudaStreamWaitEvent(sB, evM0, 0);
    k_agg<<<agg_grid, 256, 0, sB>>>(HI(6), LO(6), rowptr, ssrc, HI(1), LO(1), HI(2), LO(2), n);
    cudaEventRecord(evAggM0, sB);

    // main: mid1 (uses agg(s1) in slots 0,3)
    cudaStreamWaitEvent(0, evAggS1, 0);
    gemm1(5, 0, 3, 15, b_mid + 3 * DD, 5);
    k_combine1<<<ew_grid4, 256>>>(yb, ST(5), w_mid + 3, g_midP + 1 * 3 * DD,
                                  be_mid + 1 * 3 * DD, HI(7), LO(7), n);     // m1
    // agg(m1) -> slots 4(mean),0(max)  (slot 4 free after mid0 gemm, slot 0 after mid1 gemm)
    k_agg<<<agg_grid, 256>>>(HI(7), LO(7), rowptr, ssrc, HI(4), LO(4), HI(0), LO(0), n);

    // ---- last ops ----
    cudaStreamWaitEvent(0, evAggM0, 0);
    gemm2(6, 1, 2, 7, 4, 0, 18, b_last, 6);
    k_combine2<<<ew_grid4, 256>>>(
        yb, ST(6), w_last + 0, g_lastP + 0 * 3 * DD, be_last + 0 * 3 * DD,
        yb + 3 * ystride, ST(7), w_last + 3, g_lastP + 1 * 3 * DD, be_last + 1 * 3 * DD,
        HI(8), LO(8), n);                                    // sl

    // ---- final: cat GEMM + column-norm ----
    k_gemm_mma<<<dim3(gtiles, 1, 1), 256, SMEM_MMA>>>(
        HI(6), LO(6), HI(7), LO(7), HI(8), LO(8),
        nullptr, nullptr, nullptr, nullptr, nullptr, nullptr,
        wpre + 24L * 16384, b_cat, yb, ST(8), n, ystride, 1);
    k_finalnorm<<<ew_grid, 256>>>(yb, ST(8), g_cat, be_cat, (float*)d_out, n);
}

// round 14
// speedup vs baseline: 1.0760x; 1.0065x over previous
#include <cuda_runtime.h>
#include <cuda_fp16.h>
#include <cstdint>
#include <math_constants.h>

#define NN 100000
#define EE 600000
#define DD 128
#define EPSLN 1e-5f
#define PLANE ((size_t)(NN + 128) * DD)   // padded hi/lo plane (tail rows read as 0)

// ---------------- scratch (device globals) -------------------------------------
__device__ float g_y[9L * NN * DD];          // 9 y planes (concurrent GEMMs)
__device__ float g_statsA[9 * 2 * 3 * DD];
__device__ int   g_deg[NN];
__device__ int   g_rowptr[NN + 1];
__device__ int   g_cursor[NN];
__device__ int   g_ssrc[EE];
__device__ int   g_bsums[256];
__device__ __half g_wpre[27L * 16384];
__device__ __half g_hlhi[9 * PLANE];
__device__ __half g_hllo[9 * PLANE];

// ---------------- helpers ------------------------------------------------------
__device__ __forceinline__ uint32_t smem_u32(const void* p) {
    uint32_t a;
    asm("{ .reg .u64 t; cvta.to.shared.u64 t, %1; cvt.u32.u64 %0, t; }" : "=r"(a) : "l"(p));
    return a;
}
__device__ __forceinline__ uint32_t pkh(__half a, __half b) {
    return (uint32_t)__half_as_ushort(a) | ((uint32_t)__half_as_ushort(b) << 16);
}
__device__ __forceinline__ void split4(float4 v, uint2& hi, uint2& lo) {
    __half h0 = __float2half_rn(v.x), h1 = __float2half_rn(v.y);
    __half h2 = __float2half_rn(v.z), h3 = __float2half_rn(v.w);
    __half l0 = __float2half_rn(v.x - __half2float(h0));
    __half l1 = __float2half_rn(v.y - __half2float(h1));
    __half l2 = __float2half_rn(v.z - __half2float(h2));
    __half l3 = __float2half_rn(v.w - __half2float(h3));
    hi = make_uint2(pkh(h0, h1), pkh(h2, h3));
    lo = make_uint2(pkh(l0, l1), pkh(l2, l3));
}
__device__ __forceinline__ float4 join4(uint2 hi, uint2 lo) {
    __half2 h01 = *(__half2*)&hi.x, h23 = *(__half2*)&hi.y;
    __half2 l01 = *(__half2*)&lo.x, l23 = *(__half2*)&lo.y;
    float2 a = __half22float2(h01), b = __half22float2(h23);
    float2 c = __half22float2(l01), d = __half22float2(l23);
    return make_float4(a.x + c.x, a.y + c.y, b.x + d.x, b.y + d.y);
}
__device__ __forceinline__ void ldsm_x4(uint32_t& r0, uint32_t& r1, uint32_t& r2, uint32_t& r3,
                                        uint32_t addr) {
    asm volatile("ldmatrix.sync.aligned.m8n8.x4.shared.b16 {%0, %1, %2, %3}, [%4];"
                 : "=r"(r0), "=r"(r1), "=r"(r2), "=r"(r3) : "r"(addr));
}
__device__ __forceinline__ void mma16816h(float* c, const uint32_t* a, const uint32_t* b) {
    asm volatile(
        "mma.sync.aligned.m16n8k16.row.col.f32.f16.f16.f32 "
        "{%0, %1, %2, %3}, {%4, %5, %6, %7}, {%8, %9}, {%0, %1, %2, %3};"
        : "+f"(c[0]), "+f"(c[1]), "+f"(c[2]), "+f"(c[3])
        : "r"(a[0]), "r"(a[1]), "r"(a[2]), "r"(a[3]), "r"(b[0]), "r"(b[1]));
}
__device__ __forceinline__ void cpasync16(uint32_t saddr, const void* gaddr) {
    asm volatile("cp.async.cg.shared.global [%0], [%1], 16;" :: "r"(saddr), "l"(gaddr));
}
__device__ __forceinline__ void cpasync_commit() {
    asm volatile("cp.async.commit_group;");
}
__device__ __forceinline__ void cpasync_wait0() {
    asm volatile("cp.async.wait_group 0;");
}

// ---------------- weight prep ---------------------------------------------------
__global__ void k_wprep(const float* __restrict__ W, __half* __restrict__ out,
                        float* statszero, int zn) {
    if (statszero && blockIdx.x == 0) {
        for (int i = threadIdx.x; i < zn; i += blockDim.x) statszero[i] = 0.f;
    }
    int m = blockIdx.x >> 3;
    int part = blockIdx.x & 7;
    const float* src = W + (size_t)m * 16384;
    __half* oh = out + (size_t)m * 16384;
    int base = part * 2048;
    for (int i = threadIdx.x; i < 2048; i += blockDim.x) {
        int idx = base + i;
        int d = idx >> 7, f = idx & 127;
        oh[f * 128 + d] = __float2half_rn(src[idx]);
    }
}

// ---------------- zero-op candidates -> hi/lo planes ---------------------------
__global__ void k_pre_hl(const float* __restrict__ a, const float* __restrict__ b,
                         __half* h0, __half* l0, __half* h1, __half* l1,
                         __half* h2, __half* l2, int total4) {
    int i4 = blockIdx.x * blockDim.x + threadIdx.x;
    if (i4 >= total4) return;
    float4 x = ((const float4*)a)[i4];
    float4 y = ((const float4*)b)[i4];
    uint2 hi, lo;
    split4(x, hi, lo);
    ((uint2*)h0)[i4] = hi; ((uint2*)l0)[i4] = lo;
    float4 d = make_float4(x.x - y.x, x.y - y.y, x.z - y.z, x.w - y.w);
    split4(d, hi, lo);
    ((uint2*)h1)[i4] = hi; ((uint2*)l1)[i4] = lo;
    float4 p = make_float4(x.x * y.x, x.y * y.y, x.z * y.z, x.w * y.w);
    split4(p, hi, lo);
    ((uint2*)h2)[i4] = hi; ((uint2*)l2)[i4] = lo;
}

// ---------------- fp16 2-pass tensor GEMM, double-buffered swizzled fills -------
#define TILE_BYTES 16384
#define BUFBYTES (3 * TILE_BYTES)
#define SMEM_MMA (2 * BUFBYTES + 1024)

__global__ __launch_bounds__(256, 2) void k_gemm_mma(
    const __half* __restrict__ a0h, const __half* __restrict__ a0l,
    const __half* __restrict__ a1h, const __half* __restrict__ a1l,
    const __half* __restrict__ a2h, const __half* __restrict__ a2l,
    const __half* __restrict__ b0h, const __half* __restrict__ b0l,
    const __half* __restrict__ b1h, const __half* __restrict__ b1l,
    const __half* __restrict__ b2h, const __half* __restrict__ b2l,
    const __half* __restrict__ wpre, const float* __restrict__ bias,
    float* __restrict__ Y, float* __restrict__ stats, int n, size_t ystride,
    int catmode, int ybase)
{
    extern __shared__ char sm[];
    float* ssum = (float*)(sm + 2 * BUFBYTES);
    float* ssq  = ssum + 128;

    int tid = threadIdx.x;
    int wid = tid >> 5, lane = tid & 31;
    int wm_ = wid >> 1, wn_ = wid & 1;
    int z = blockIdx.z;
    int opsel = z / 3;
    int kcand = catmode ? 0 : (z % 3);
    int nchunk = catmode ? 3 : 1;
    int row0 = blockIdx.x * 128;
    float* Yk = Y + (size_t)(ybase + opsel * 3 + kcand) * ystride;
    const float* bk = bias + (opsel * 3 + kcand) * DD;
    float* st = stats + opsel * 768;
    int so = kcand * DD;

    if (tid < 128) { ssum[tid] = 0.f; ssq[tid] = 0.f; }

    float c[2][8][4];
    #pragma unroll
    for (int i = 0; i < 2; i++)
        #pragma unroll
        for (int j = 0; j < 8; j++)
            #pragma unroll
            for (int q = 0; q < 4; q++) c[i][j][q] = 0.f;

    int a_row = wm_ * 32 + (lane & 15);
    int a_cs = lane >> 4;
    int b_f = wn_ * 64 + ((lane >> 4) << 3) + (lane & 7);
    int b_cs = (lane >> 3) & 1;
    uint32_t ubase = smem_u32(sm);

    const __half* XHt[3];
    const __half* XLt[3];
    if (opsel == 0 || catmode) {
        XHt[0] = a0h; XHt[1] = a1h; XHt[2] = a2h;
        XLt[0] = a0l; XLt[1] = a1l; XLt[2] = a2l;
    } else {
        XHt[0] = b0h; XHt[1] = b1h; XHt[2] = b2h;
        XLt[0] = b0l; XLt[1] = b1l; XLt[2] = b2l;
    }

    int totchunks = nchunk * 2;
    int frow = tid >> 1, fsg = tid & 1;

    auto do_fill = [&](int tc, int buf) {
        int c3 = tc >> 1, ch = tc & 1;
        const __half* XH = catmode ? XHt[c3] : XHt[kcand];
        const __half* XL = catmode ? XLt[c3] : XLt[kcand];
        const __half* wmr = wpre + (size_t)(opsel * 3 + (catmode ? c3 : kcand)) * 16384;
        uint32_t bb = ubase + (uint32_t)(buf * BUFBYTES);
        size_t gofs = ((size_t)(row0 + frow) * DD + ch * 64) * 2 + fsg * 64;
        const char* sh = (const char*)XH + gofs;
        const char* sl = (const char*)XL + gofs;
        const char* sb = (const char*)wmr + ((size_t)frow * 128 + ch * 64) * 2 + fsg * 64;
        uint32_t rowbase = (uint32_t)(frow * 128);
        uint32_t rsw = (uint32_t)(frow & 7);
        #pragma unroll
        for (int q = 0; q < 4; q++) {
            uint32_t slot = (uint32_t)(((fsg * 4 + q) ^ rsw) << 4);
            cpasync16(bb + rowbase + slot, sh + q * 16);
            cpasync16(bb + TILE_BYTES + rowbase + slot, sl + q * 16);
            cpasync16(bb + 2 * TILE_BYTES + rowbase + slot, sb + q * 16);
        }
        cpasync_commit();
    };

    do_fill(0, 0);
    for (int tc = 0; tc < totchunks; tc++) {
        cpasync_wait0();
        __syncthreads();
        if (tc + 1 < totchunks) do_fill(tc + 1, (tc + 1) & 1);
        uint32_t bb = ubase + (uint32_t)((tc & 1) * BUFBYTES);
        uint32_t uAhi = bb;
        uint32_t uAlo = bb + TILE_BYTES;
        uint32_t uBh  = bb + 2 * TILE_BYTES;
        #pragma unroll
        for (int k = 0; k < 4; k++) {
            uint32_t ah[2][4], al[2][4];
            #pragma unroll
            for (int mt = 0; mt < 2; mt++) {
                int ra = a_row + mt * 16;
                uint32_t off = (uint32_t)(ra * 128 + (((2 * k + a_cs) ^ (ra & 7)) << 4));
                ldsm_x4(ah[mt][0], ah[mt][1], ah[mt][2], ah[mt][3], uAhi + off);
                ldsm_x4(al[mt][0], al[mt][1], al[mt][2], al[mt][3], uAlo + off);
            }
            uint32_t b[4][4];
            #pragma unroll
            for (int p = 0; p < 4; p++) {
                int rb = b_f + p * 16;
                uint32_t off = (uint32_t)(rb * 128 + (((2 * k + b_cs) ^ (rb & 7)) << 4));
                ldsm_x4(b[p][0], b[p][1], b[p][2], b[p][3], uBh + off);
            }
            #pragma unroll
            for (int mt = 0; mt < 2; mt++)
                #pragma unroll
                for (int nt = 0; nt < 8; nt++) {
                    mma16816h(c[mt][nt], ah[mt], &b[nt >> 1][(nt & 1) * 2]);
                    mma16816h(c[mt][nt], al[mt], &b[nt >> 1][(nt & 1) * 2]);
                }
        }
    }

    int erow = lane >> 2, ecp = lane & 3;
    float2 bb2[8];
    #pragma unroll
    for (int nt = 0; nt < 8; nt++)
        bb2[nt] = *(const float2*)(bk + wn_ * 64 + nt * 8 + ecp * 2);

    float lsum[16], lsq[16];
    #pragma unroll
    for (int j = 0; j < 16; j++) { lsum[j] = 0.f; lsq[j] = 0.f; }

    #pragma unroll
    for (int mt = 0; mt < 2; mt++) {
        int r0g = row0 + wm_ * 32 + mt * 16 + erow;
        int r1g = r0g + 8;
        #pragma unroll
        for (int nt = 0; nt < 8; nt++) {
            int cbase = wn_ * 64 + nt * 8 + ecp * 2;
            float v00 = c[mt][nt][0] + bb2[nt].x;
            float v01 = c[mt][nt][1] + bb2[nt].y;
            float v10 = c[mt][nt][2] + bb2[nt].x;
            float v11 = c[mt][nt][3] + bb2[nt].y;
            if (r0g < n) {
                *(float2*)(Yk + (size_t)r0g * DD + cbase) = make_float2(v00, v01);
                lsum[nt * 2]     += v00; lsq[nt * 2]     += v00 * v00;
                lsum[nt * 2 + 1] += v01; lsq[nt * 2 + 1] += v01 * v01;
            }
            if (r1g < n) {
                *(float2*)(Yk + (size_t)r1g * DD + cbase) = make_float2(v10, v11);
                lsum[nt * 2]     += v10; lsq[nt * 2]     += v10 * v10;
                lsum[nt * 2 + 1] += v11; lsq[nt * 2 + 1] += v11 * v11;
            }
        }
    }
    #pragma unroll
    for (int nt = 0; nt < 8; nt++) {
        int cbase = wn_ * 64 + nt * 8 + ecp * 2;
        atomicAdd(&ssum[cbase],     lsum[nt * 2]);
        atomicAdd(&ssq[cbase],      lsq[nt * 2]);
        atomicAdd(&ssum[cbase + 1], lsum[nt * 2 + 1]);
        atomicAdd(&ssq[cbase + 1],  lsq[nt * 2 + 1]);
    }
    __syncthreads();
    if (tid < 128) {
        atomicAdd(&st[so + tid], ssum[tid]);
        atomicAdd(&st[3 * DD + so + tid], ssq[tid]);
    }
}

// ---------------- CSR build ---------------------------------------------------
__global__ void k_hist(const int* __restrict__ dst, int* deg, int e) {
    int i = blockIdx.x * blockDim.x + threadIdx.x;
    if (i < e) atomicAdd(&deg[dst[i]], 1);
}
__global__ void k_scan_block(const int* __restrict__ deg, int* incl, int* bsums, int n) {
    __shared__ int sh[1024];
    int i = blockIdx.x * 1024 + threadIdx.x;
    int v = (i < n) ? deg[i] : 0;
    sh[threadIdx.x] = v;
    __syncthreads();
    for (int off = 1; off < 1024; off <<= 1) {
        int t = (threadIdx.x >= off) ? sh[threadIdx.x - off] : 0;
        __syncthreads();
        sh[threadIdx.x] += t;
        __syncthreads();
    }
    if (i < n) incl[i] = sh[threadIdx.x];
    if (threadIdx.x == 1023) bsums[blockIdx.x] = sh[1023];
}
__global__ void k_scan_sums(int* bsums, int nb) {
    if (threadIdx.x == 0 && blockIdx.x == 0) {
        int run = 0;
        for (int i = 0; i < nb; i++) { int t = bsums[i]; bsums[i] = run; run += t; }
    }
}
__global__ void k_scan_fin(const int* __restrict__ deg, const int* __restrict__ incl,
                           const int* __restrict__ bsums, int* rowptr, int* cursor, int n, int e) {
    int i = blockIdx.x * blockDim.x + threadIdx.x;
    if (i < n) {
        int ex = incl[i] - deg[i] + bsums[i >> 10];
        rowptr[i] = ex;
        cursor[i] = ex;
        if (i == n - 1) rowptr[n] = e;
    }
}
__global__ void k_scatter(const int* __restrict__ src, const int* __restrict__ dst,
                          int* cursor, int* ssrc, int e) {
    int i = blockIdx.x * blockDim.x + threadIdx.x;
    if (i < e) {
        int p = atomicAdd(&cursor[dst[i]], 1);
        ssrc[p] = src[i];
    }
}

// ---------------- graph aggregation: planes in -> planes out -------------------
__global__ void k_agg(const __half* __restrict__ hH, const __half* __restrict__ hL,
                      const int* __restrict__ rowptr, const int* __restrict__ ssrc,
                      __half* mhi, __half* mlo, __half* xhi, __half* xlo, int n) {
    int warp = (blockIdx.x * blockDim.x + threadIdx.x) >> 5;
    int lane = threadIdx.x & 31;
    if (warp >= n) return;
    int beg = rowptr[warp], end = rowptr[warp + 1];
    float4 s  = make_float4(0.f, 0.f, 0.f, 0.f);
    float4 mx = make_float4(-CUDART_INF_F, -CUDART_INF_F, -CUDART_INF_F, -CUDART_INF_F);
    for (int i = beg; i < end; i++) {
        int src = ssrc[i];
        uint2 hi = ((const uint2*)(hH + (size_t)src * DD))[lane];
        uint2 lo = ((const uint2*)(hL + (size_t)src * DD))[lane];
        float4 v = join4(hi, lo);
        s.x += v.x; s.y += v.y; s.z += v.z; s.w += v.w;
        mx.x = fmaxf(mx.x, v.x); mx.y = fmaxf(mx.y, v.y);
        mx.z = fmaxf(mx.z, v.z); mx.w = fmaxf(mx.w, v.w);
    }
    int deg = end - beg;
    float inv = 1.0f / (float)max(deg, 1);
    float4 mo = make_float4(s.x * inv, s.y * inv, s.z * inv, s.w * inv);
    float4 xo = (deg > 0) ? mx : make_float4(0.f, 0.f, 0.f, 0.f);
    uint2 hi, lo;
    split4(mo, hi, lo);
    ((uint2*)(mhi + (size_t)warp * DD))[lane] = hi;
    ((uint2*)(mlo + (size_t)warp * DD))[lane] = lo;
    split4(xo, hi, lo);
    ((uint2*)(xhi + (size_t)warp * DD))[lane] = hi;
    ((uint2*)(xlo + (size_t)warp * DD))[lane] = lo;
}

// ---------------- combine: normalize+relu+ksum -> hi/lo planes ------------------
__device__ __forceinline__ float4 mix3(const float* y, const float* stats,
                                       const float* wrow, const float* gg,
                                       const float* be, int i4, int d0, float fn,
                                       size_t plane_elts) {
    float4 acc = make_float4(0.f, 0.f, 0.f, 0.f);
    #pragma unroll
    for (int k = 0; k < 3; k++) {
        float wk = wrow[k];
        float4 v = ((const float4*)(y + (size_t)k * plane_elts))[i4];
        #pragma unroll
        for (int j = 0; j < 4; j++) {
            int d = d0 + j;
            float mu  = stats[k * DD + d] / fn;
            float var = stats[3 * DD + k * DD + d] / fn - mu * mu;
            float rs  = rsqrtf(var + EPSLN);
            float vv = (&v.x)[j];
            float t = (vv - mu) * rs * gg[k * DD + d] + be[k * DD + d];
            (&acc.x)[j] += wk * fmaxf(t, 0.f);
        }
    }
    return acc;
}

__global__ void k_combine1(const float* __restrict__ y, const float* __restrict__ stats,
                           const float* __restrict__ wrow, const float* __restrict__ gg,
                           const float* __restrict__ be,
                           __half* hiP, __half* loP, int n) {
    int i4 = blockIdx.x * blockDim.x + threadIdx.x;
    int total4 = (n * DD) >> 2;
    if (i4 >= total4) return;
    int d0 = (i4 << 2) & (DD - 1);
    float4 acc = mix3(y, stats, wrow, gg, be, i4, d0, (float)n, (size_t)n * DD);
    uint2 hi, lo;
    split4(acc, hi, lo);
    ((uint2*)hiP)[i4] = hi;
    ((uint2*)loP)[i4] = lo;
}

__global__ void k_combine2(const float* __restrict__ yA, const float* __restrict__ stA,
                           const float* __restrict__ wA, const float* __restrict__ gA,
                           const float* __restrict__ beA,
                           const float* __restrict__ yB, const float* __restrict__ stB,
                           const float* __restrict__ wB, const float* __restrict__ gB,
                           const float* __restrict__ beB,
                           __half* hiP, __half* loP, int n) {
    int i4 = blockIdx.x * blockDim.x + threadIdx.x;
    int total4 = (n * DD) >> 2;
    if (i4 >= total4) return;
    int d0 = (i4 << 2) & (DD - 1);
    float fn = (float)n;
    size_t pe = (size_t)n * DD;
    float4 a = mix3(yA, stA, wA, gA, beA, i4, d0, fn, pe);
    float4 b = mix3(yB, stB, wB, gB, beB, i4, d0, fn, pe);
    float4 acc = make_float4(a.x + b.x, a.y + b.y, a.z + b.z, a.w + b.w);
    uint2 hi, lo;
    split4(acc, hi, lo);
    ((uint2*)hiP)[i4] = hi;
    ((uint2*)loP)[i4] = lo;
}

// ---------------- final column-norm + relu ------------------------------------
__global__ void k_finalnorm(const float* __restrict__ h, const float* __restrict__ stats,
                            const float* __restrict__ gc, const float* __restrict__ bec,
                            float* __restrict__ out, int n) {
    int idx = blockIdx.x * blockDim.x + threadIdx.x;
    int total = n * DD;
    if (idx >= total) return;
    int d = idx & (DD - 1);
    float fn = (float)n;
    float mu  = stats[d] / fn;
    float var = stats[3 * DD + d] / fn - mu * mu;
    float rs  = rsqrtf(var + EPSLN);
    float v = (h[idx] - mu) * rs * gc[d] + bec[d];
    out[idx] = fmaxf(v, 0.f);
}

// ---------------- host orchestration (multi-stream fork/join) -------------------
extern "C" void kernel_launch(void* const* d_in, const int* in_sizes, int n_in,
                              void* d_out, int out_size) {
    const float* src_emb = (const float*)d_in[0];
    const float* hr      = (const float*)d_in[1];
    const int*   esrc    = (const int*)d_in[2];
    const int*   edst    = (const int*)d_in[3];
    const float* w_zero  = (const float*)d_in[4];
    const float* w_first = (const float*)d_in[5];
    const float* w_mid   = (const float*)d_in[6];
    const float* w_last  = (const float*)d_in[7];
    const float* W_zero  = (const float*)d_in[8];
    const float* b_zero  = (const float*)d_in[9];
    const float* g_zeroP = (const float*)d_in[10];
    const float* be_zero = (const float*)d_in[11];
    const float* W_first = (const float*)d_in[12];
    const float* b_first = (const float*)d_in[13];
    const float* g_firstP= (const float*)d_in[14];
    const float* be_first= (const float*)d_in[15];
    const float* W_mid   = (const float*)d_in[16];
    const float* b_mid   = (const float*)d_in[17];
    const float* g_midP  = (const float*)d_in[18];
    const float* be_mid  = (const float*)d_in[19];
    const float* W_last  = (const float*)d_in[20];
    const float* b_last  = (const float*)d_in[21];
    const float* g_lastP = (const float*)d_in[22];
    const float* be_last = (const float*)d_in[23];
    const float* W_cat   = (const float*)d_in[24];
    const float* b_cat   = (const float*)d_in[25];
    const float* g_cat   = (const float*)d_in[26];
    const float* be_cat  = (const float*)d_in[27];

    int n = in_sizes[0] / DD;
    int e = in_sizes[2];

    float *yb, *statsA;
    int *deg, *rowptr, *cursor, *ssrc, *bsums;
    __half *wpre, *hlhi, *hllo;
    cudaGetSymbolAddress((void**)&yb, g_y);
    cudaGetSymbolAddress((void**)&statsA, g_statsA);
    cudaGetSymbolAddress((void**)&deg, g_deg);
    cudaGetSymbolAddress((void**)&rowptr, g_rowptr);
    cudaGetSymbolAddress((void**)&cursor, g_cursor);
    cudaGetSymbolAddress((void**)&ssrc, g_ssrc);
    cudaGetSymbolAddress((void**)&bsums, g_bsums);
    cudaGetSymbolAddress((void**)&wpre, g_wpre);
    cudaGetSymbolAddress((void**)&hlhi, g_hlhi);
    cudaGetSymbolAddress((void**)&hllo, g_hllo);

    static cudaStream_t sA = nullptr, sB = nullptr;
    static cudaEvent_t evFork, evWprep, evCsr, evAggS0, evF2, evMid0g, evM0A;
    if (!sA) {
        cudaStreamCreateWithFlags(&sA, cudaStreamNonBlocking);
        cudaStreamCreateWithFlags(&sB, cudaStreamNonBlocking);
        cudaEventCreateWithFlags(&evFork, cudaEventDisableTiming);
        cudaEventCreateWithFlags(&evWprep, cudaEventDisableTiming);
        cudaEventCreateWithFlags(&evCsr, cudaEventDisableTiming);
        cudaEventCreateWithFlags(&evAggS0, cudaEventDisableTiming);
        cudaEventCreateWithFlags(&evF2, cudaEventDisableTiming);
        cudaEventCreateWithFlags(&evMid0g, cudaEventDisableTiming);
        cudaEventCreateWithFlags(&evM0A, cudaEventDisableTiming);
        cudaFuncSetAttribute(k_gemm_mma, cudaFuncAttributeMaxDynamicSharedMemorySize, SMEM_MMA);
    }

    auto HI = [&](int s) { return hlhi + (size_t)s * PLANE; };
    auto LO = [&](int s) { return hllo + (size_t)s * PLANE; };
    auto ST = [&](int s) { return statsA + (size_t)s * 768; };

    int total = n * DD;
    size_t ystride = (size_t)n * DD;
    int gtiles = (n + 127) / 128;
    int ew_grid = (total + 255) / 256;
    int ew_grid4 = (total / 4 + 255) / 256;
    int agg_grid = (n + 7) / 8;
    int eb = (e + 255) / 256;
    int nb1024 = (n + 1023) / 1024;

    auto gemm1 = [&](cudaStream_t str, int c0, int c1, int c2, int opmat,
                     const float* B, int stslot, int ybase) {
        k_gemm_mma<<<dim3(gtiles, 1, 3), 256, SMEM_MMA, str>>>(
            HI(c0), LO(c0), HI(c1), LO(c1), HI(c2), LO(c2),
            nullptr, nullptr, nullptr, nullptr, nullptr, nullptr,
            wpre + (size_t)opmat * 16384, B, yb, ST(stslot), n, ystride, 0, ybase);
    };
    auto gemm2 = [&](int a0, int a1, int a2, int b0, int b1, int b2,
                     int opmat, const float* B, int stslot) {
        k_gemm_mma<<<dim3(gtiles, 1, 6), 256, SMEM_MMA>>>(
            HI(a0), LO(a0), HI(a1), LO(a1), HI(a2), LO(a2),
            HI(b0), LO(b0), HI(b1), LO(b1), HI(b2), LO(b2),
            wpre + (size_t)opmat * 16384, B, yb, ST(stslot), n, ystride, 0, 0);
    };

    // ---- fork ----
    cudaEventRecord(evFork, 0);

    // side A: remaining weight preps
    cudaStreamWaitEvent(sA, evFork, 0);
    k_wprep<<<9 * 8, 256, 0, sA>>>(W_first, wpre + 3L  * 16384, nullptr, 0);
    k_wprep<<<6 * 8, 256, 0, sA>>>(W_mid,   wpre + 12L * 16384, nullptr, 0);
    k_wprep<<<6 * 8, 256, 0, sA>>>(W_last,  wpre + 18L * 16384, nullptr, 0);
    k_wprep<<<3 * 8, 256, 0, sA>>>(W_cat,   wpre + 24L * 16384, nullptr, 0);
    cudaEventRecord(evWprep, sA);

    // side B: CSR build
    cudaStreamWaitEvent(sB, evFork, 0);
    cudaMemsetAsync(deg, 0, (size_t)n * sizeof(int), sB);
    k_hist<<<eb, 256, 0, sB>>>(edst, deg, e);
    k_scan_block<<<nb1024, 1024, 0, sB>>>(deg, cursor, bsums, n);
    k_scan_sums<<<1, 32, 0, sB>>>(bsums, nb1024);
    k_scan_fin<<<(n + 255) / 256, 256, 0, sB>>>(deg, cursor, bsums, rowptr, cursor, n, e);
    k_scatter<<<eb, 256, 0, sB>>>(esrc, edst, cursor, ssrc, e);
    cudaEventRecord(evCsr, sB);

    // main: zero op
    k_wprep<<<3 * 8, 256>>>(W_zero, wpre + 0L * 16384, statsA, 9 * 768);
    k_pre_hl<<<ew_grid4, 256>>>(src_emb, hr, HI(0), LO(0), HI(1), LO(1), HI(2), LO(2), total / 4);
    gemm1(0, 0, 1, 2, 0, b_zero, 0, 0);
    k_combine1<<<ew_grid4, 256>>>(yb, ST(0), w_zero, g_zeroP, be_zero, HI(3), LO(3), n);

    // ---- first ops ----
    cudaStreamWaitEvent(0, evCsr, 0);
    k_agg<<<agg_grid, 256>>>(HI(3), LO(3), rowptr, ssrc, HI(1), LO(1), HI(2), LO(2), n);
    cudaStreamWaitEvent(0, evWprep, 0);
    gemm2(3, 1, 2, 3, 1, 2, 3, b_first, 1);                  // first0 -> y0-2/ST1, first1 -> y3-5/ST2
    k_combine1<<<ew_grid4, 256>>>(yb, ST(1), w_first + 0, g_firstP + 0 * 3 * DD,
                                  be_first + 0 * 3 * DD, HI(4), LO(4), n);   // s0
    k_agg<<<agg_grid, 256>>>(HI(4), LO(4), rowptr, ssrc, HI(1), LO(1), HI(2), LO(2), n);
    cudaEventRecord(evAggS0, 0);

    // main: first2 -> y0-2/ST3
    gemm1(0, 4, 1, 2, 9, b_first + 6 * DD, 3, 0);
    cudaEventRecord(evF2, 0);

    // side A: mid0 chain, concurrent with first2/combine2(s1)/mid1
    cudaStreamWaitEvent(sA, evAggS0, 0);
    gemm1(sA, 4, 1, 2, 12, b_mid, 4, 6);                     // mid0 -> y6-8/ST4
    cudaEventRecord(evMid0g, sA);
    k_combine1<<<ew_grid4, 256, 0, sA>>>(yb + 6 * ystride, ST(4), w_mid + 0,
                                         g_midP + 0 * 3 * DD, be_mid + 0 * 3 * DD,
                                         HI(6), LO(6), n);   // m0
    cudaStreamWaitEvent(sA, evF2, 0);                        // slots 1,2 free after first2
    k_agg<<<agg_grid, 256, 0, sA>>>(HI(6), LO(6), rowptr, ssrc, HI(1), LO(1), HI(2), LO(2), n);
    cudaEventRecord(evM0A, sA);

    // main: s1 = first1 + first2 -> slot5
    k_combine2<<<ew_grid4, 256>>>(
        yb + 3 * ystride, ST(2), w_first + 3, g_firstP + 1 * 3 * DD, be_first + 1 * 3 * DD,
        yb, ST(3), w_first + 6, g_firstP + 2 * 3 * DD, be_first + 2 * 3 * DD,
        HI(5), LO(5), n);
    // agg(s1) -> slots 0(mean),3(max)
    k_agg<<<agg_grid, 256>>>(HI(5), LO(5), rowptr, ssrc, HI(0), LO(0), HI(3), LO(3), n);
    // mid1 -> y3-5/ST5
    gemm1(0, 5, 0, 3, 15, b_mid + 3 * DD, 5, 3);
    k_combine1<<<ew_grid4, 256>>>(yb + 3 * ystride, ST(5), w_mid + 3,
                                  g_midP + 1 * 3 * DD, be_mid + 1 * 3 * DD,
                                  HI(7), LO(7), n);          // m1
    // agg(m1) -> slots 4(mean),0(max); slot4 needs sA's mid0 gemm done reading it
    cudaStreamWaitEvent(0, evMid0g, 0);
    k_agg<<<agg_grid, 256>>>(HI(7), LO(7), rowptr, ssrc, HI(4), LO(4), HI(0), LO(0), n);

    // ---- last ops ----
    cudaStreamWaitEvent(0, evM0A, 0);
    gemm2(6, 1, 2, 7, 4, 0, 18, b_last, 6);                  // last0 -> y0-2/ST6, last1 -> y3-5/ST7
    k_combine2<<<ew_grid4, 256>>>(
        yb, ST(6), w_last + 0, g_lastP + 0 * 3 * DD, be_last + 0 * 3 * DD,
        yb + 3 * ystride, ST(7), w_last + 3, g_lastP + 1 * 3 * DD, be_last + 1 * 3 * DD,
        HI(8), LO(8), n);                                    // sl

    // ---- final: cat GEMM + column-norm ----
    k_gemm_mma<<<dim3(gtiles, 1, 1), 256, SMEM_MMA>>>(
        HI(6), LO(6), HI(7), LO(7), HI(8), LO(8),
        nullptr, nullptr, nullptr, nullptr, nullptr, nullptr,
        wpre + 24L * 16384, b_cat, yb, ST(8), n, ystride, 1, 0);
    k_finalnorm<<<ew_grid, 256>>>(yb, ST(8), g_cat, be_cat, (float*)d_out, n);
}